// round 14
// baseline (speedup 1.0000x reference)
#include <cuda_runtime.h>
#include <cuda_fp16.h>
#include <math.h>
#include <stdint.h>

#define Bn   16
#define Ss   512
#define Dd   512
#define Hh   8
#define HSs  2
#define DFFf 2048
#define NGATE 6   // H - HS
#define QVLD 1024 // combined q||v row stride

// ---------------- scratch (device globals; no allocation allowed) ----------------
__device__ float g_y[Bn*Ss*Dd];
__device__ float g_x[Bn*Ss*Dd];
__device__ float g_tmp[Bn*Ss*Dd];
__device__ float g_rmask[Bn*Hh];
__device__ float g_bqv[6*QVLD];
__device__ float g_wgt[6*NGATE*Dd];       // per layer: [6 gates][512 d] fp32
// half activations
__device__ __half g_xh[Bn*Ss*Dd];
__device__ __half g_yh[Bn*Ss*Dd];
__device__ __half g_qvh[Bn*Ss*QVLD];      // q (cols 0-511) || v (512-1023)
__device__ __half g_ctxh[Bn*Ss*Dd];
__device__ __half g_ffnh[Bn*Ss*DFFf];
// transposed half weights
__device__ __half g_wqvh[6*QVLD*Dd];      // per layer: [1024 n][512 k], q rows then v rows
__device__ __half g_woh[6*Dd*Dd];
__device__ __half g_fw1h[6*Dd*DFFf];      // per layer: [DFF][D]
__device__ __half g_fw2h[6*DFFf*Dd];      // per layer: [D][DFF]

// ---------------- helpers ----------------
__device__ __forceinline__ void mma_f16(float c[4], uint32_t a0, uint32_t a1,
                                        uint32_t a2, uint32_t a3,
                                        uint32_t b0, uint32_t b1) {
    asm volatile(
        "mma.sync.aligned.m16n8k16.row.col.f32.f16.f16.f32 "
        "{%0,%1,%2,%3}, {%4,%5,%6,%7}, {%8,%9}, {%0,%1,%2,%3};"
        : "+f"(c[0]), "+f"(c[1]), "+f"(c[2]), "+f"(c[3])
        : "r"(a0), "r"(a1), "r"(a2), "r"(a3), "r"(b0), "r"(b1));
}

#define LDSM_X4(r0, r1, r2, r3, addr) \
    asm volatile("ldmatrix.sync.aligned.m8n8.x4.shared.b16 {%0,%1,%2,%3}, [%4];" \
                 : "=r"(r0), "=r"(r1), "=r"(r2), "=r"(r3) : "r"(addr))

__device__ __forceinline__ uint32_t smem_u32(const void* p) {
    uint32_t a;
    asm("{ .reg .u64 t; cvta.to.shared.u64 t, %1; cvt.u32.u64 %0, t; }"
        : "=r"(a) : "l"(p));
    return a;
}

__device__ __forceinline__ void cp_async16(uint32_t dst, const void* src) {
    asm volatile("cp.async.cg.shared.global [%0], [%1], 16;" :: "r"(dst), "l"(src));
}
__device__ __forceinline__ void cp_commit() {
    asm volatile("cp.async.commit_group;" ::: "memory");
}
template<int NN>
__device__ __forceinline__ void cp_wait() {
    asm volatile("cp.async.wait_group %0;" :: "n"(NN) : "memory");
}

// ---------------- unified weight convert+transpose (ONE launch) ----------------
__global__ void transp_all_kernel(const float* __restrict__ wq, const float* __restrict__ wv,
                                  const float* __restrict__ wo, const float* __restrict__ fw1,
                                  const float* __restrict__ fw2,
                                  __half* __restrict__ wqvh, __half* __restrict__ woh,
                                  __half* __restrict__ fw1h, __half* __restrict__ fw2h)
{
    __shared__ float t[32][33];
    const long long DD = (long long)Dd * Dd;
    const long long QV = (long long)QVLD * Dd;
    const long long DF = (long long)Dd * DFFf;

    int bid = blockIdx.x;
    const float* ip; __half* op; int R, C, cx, cy;
    if (bid < 4608) {
        int seg = bid / 1536, r2 = bid % 1536;
        int l = r2 >> 8, r = r2 & 255;
        cx = r & 15; cy = r >> 4; R = Dd; C = Dd;
        if (seg == 0)      { ip = wq + l * DD; op = wqvh + l * QV; }
        else if (seg == 1) { ip = wv + l * DD; op = wqvh + l * QV + DD; }
        else               { ip = wo + l * DD; op = woh + l * DD; }
    } else {
        int r2 = bid - 4608;
        int seg = r2 >> 10, r = r2 & 1023;
        int l = (seg < 2) ? 3 : 5;
        if ((seg & 1) == 0) { ip = fw1 + l * DF; op = fw1h + l * DF; R = Dd;  C = DFFf; cx = r & 63; cy = r >> 6; }
        else                { ip = fw2 + l * DF; op = fw2h + l * DF; R = DFFf; C = Dd;  cx = r & 15; cy = r >> 4; }
    }

    int c0 = cx * 32, r0 = cy * 32;
    int x = threadIdx.x, y0 = threadIdx.y;   // (32,8)
    #pragma unroll
    for (int i = 0; i < 32; i += 8)
        t[y0 + i][x] = ip[(long long)(r0 + y0 + i) * C + c0 + x];
    __syncthreads();
    #pragma unroll
    for (int i = 0; i < 32; i += 8)
        op[(long long)(c0 + y0 + i) * R + r0 + x] = __float2half_rn(t[x][y0 + i]);
}

// ---------------- embeddings fp32 -> half + qv bias concat + wg transpose ----------------
__global__ void f2h_bias_kernel(const float* __restrict__ a, __half* __restrict__ ah,
                                const float* __restrict__ b, __half* __restrict__ bh, int n,
                                const float* __restrict__ bq, const float* __restrict__ bv,
                                float* __restrict__ bqv,
                                const float* __restrict__ wg, float* __restrict__ wgt)
{
    int i = blockIdx.x * blockDim.x + threadIdx.x;
    if (i < n) {
        ah[i] = __float2half_rn(a[i]);
        bh[i] = __float2half_rn(b[i]);
    }
    if (i < 6 * QVLD) {
        int l = i >> 10, c = i & 1023;
        bqv[i] = (c < Dd) ? bq[l * Dd + c] : bv[l * Dd + c - Dd];
    }
    if (i < 6 * NGATE * Dd) {
        int l = i / (NGATE * Dd);
        int r = i % (NGATE * Dd);
        int g = r / Dd, d = r % Dd;
        wgt[i] = wg[(long long)l * Dd * NGATE + d * NGATE + g];
    }
}

// ---------------- cp.async 3-stage FP16 GEMM (ldmatrix fragments) ----------------
#define HBM 128
#define HBN 128
#define HBK 64
#define HLDA 72
#define HSA (HBM * HLDA)           // 9216 halves
#define HSTAGE (2 * HSA)
#define H_SMEM (3 * HSTAGE * 2)    // 110592 bytes

template<int OM>
__global__ void __launch_bounds__(256) gemm_h_kernel(
    const __half* __restrict__ A, const __half* __restrict__ Bt,
    const float* __restrict__ bias, float* __restrict__ Cf, __half* __restrict__ Ch,
    int K, int Ncols, int ldc, int relu)
{
    extern __shared__ __align__(16) __half smh[];

    const int tid = threadIdx.x;
    const int warpId = tid >> 5;
    const int lane = tid & 31;
    const int grp = lane >> 2;
    const int tig = lane & 3;
    const int warpM = warpId & 1;
    const int warpN = warpId >> 1;
    const int row0 = blockIdx.y * HBM;
    const int col0 = blockIdx.x * HBN;

    const uint32_t sbase = smem_u32(smh);

    const uint32_t aOff = (uint32_t)((warpM * 64 + (lane & 15)) * HLDA + ((lane >> 4) << 3));
    const int bg = lane >> 3;
    const uint32_t bOff = (uint32_t)((warpN * 32 + ((bg >= 2) ? 8 : 0) + (lane & 7)) * HLDA
                                     + ((bg & 1) << 3));

    auto issue = [&](int kt) {
        const int st = kt % 3;
        const int k0 = kt * HBK;
        const uint32_t sA = sbase + (uint32_t)(st * HSTAGE) * 2u;
        const uint32_t sB = sA + (uint32_t)HSA * 2u;
        #pragma unroll
        for (int i = 0; i < 4; i++) {
            int f4 = tid + i * 256;
            int r = f4 >> 3, c8 = (f4 & 7) * 8;
            cp_async16(sA + (uint32_t)(r * HLDA + c8) * 2u,
                       &A[(long long)(row0 + r) * K + k0 + c8]);
        }
        #pragma unroll
        for (int i = 0; i < 4; i++) {
            int f4 = tid + i * 256;
            int n = f4 >> 3, c8 = (f4 & 7) * 8;
            cp_async16(sB + (uint32_t)(n * HLDA + c8) * 2u,
                       &Bt[(long long)(col0 + n) * K + k0 + c8]);
        }
        cp_commit();
    };

    float acc[4][4][4];
    #pragma unroll
    for (int mt = 0; mt < 4; mt++)
        #pragma unroll
        for (int nt = 0; nt < 4; nt++)
            #pragma unroll
            for (int q = 0; q < 4; q++) acc[mt][nt][q] = 0.f;

    const int KT = K / HBK;
    issue(0);
    if (KT > 1) issue(1);

    for (int kt = 0; kt < KT; kt++) {
        if (kt + 1 < KT) cp_wait<1>(); else cp_wait<0>();
        __syncthreads();
        if (kt + 2 < KT) issue(kt + 2);

        const uint32_t sA = sbase + (uint32_t)((kt % 3) * HSTAGE) * 2u;
        const uint32_t sB = sA + (uint32_t)HSA * 2u;

        #pragma unroll
        for (int kk = 0; kk < 4; kk++) {
            const uint32_t kh = (uint32_t)(kk * 16) * 2u;
            uint32_t af[4][4];
            #pragma unroll
            for (int mt = 0; mt < 4; mt++)
                LDSM_X4(af[mt][0], af[mt][1], af[mt][2], af[mt][3],
                        sA + (aOff + (uint32_t)(mt * 16 * HLDA)) * 2u + kh);
            uint32_t bf[4][2];
            LDSM_X4(bf[0][0], bf[0][1], bf[1][0], bf[1][1], sB + bOff * 2u + kh);
            LDSM_X4(bf[2][0], bf[2][1], bf[3][0], bf[3][1],
                    sB + (bOff + (uint32_t)(16 * HLDA)) * 2u + kh);
            #pragma unroll
            for (int mt = 0; mt < 4; mt++)
                #pragma unroll
                for (int nt = 0; nt < 4; nt++)
                    mma_f16(acc[mt][nt], af[mt][0], af[mt][1], af[mt][2], af[mt][3],
                            bf[nt][0], bf[nt][1]);
        }
    }

    #pragma unroll
    for (int mt = 0; mt < 4; mt++) {
        #pragma unroll
        for (int nt = 0; nt < 4; nt++) {
            int r0 = row0 + warpM * 64 + mt * 16 + grp;
            int cc = col0 + warpN * 32 + nt * 8 + tig * 2;
            float b0 = bias[cc], b1 = bias[cc + 1];
            float v0 = acc[mt][nt][0] + b0;
            float v1 = acc[mt][nt][1] + b1;
            float v2 = acc[mt][nt][2] + b0;
            float v3 = acc[mt][nt][3] + b1;
            if (relu) {
                v0 = fmaxf(v0, 0.f); v1 = fmaxf(v1, 0.f);
                v2 = fmaxf(v2, 0.f); v3 = fmaxf(v3, 0.f);
            }
            if (OM == 0) {
                *(float2*)&Cf[(long long)r0 * ldc + cc]       = make_float2(v0, v1);
                *(float2*)&Cf[(long long)(r0 + 8) * ldc + cc] = make_float2(v2, v3);
            } else {
                *(__half2*)&Ch[(long long)r0 * ldc + cc]       = __floats2half2_rn(v0, v1);
                *(__half2*)&Ch[(long long)(r0 + 8) * ldc + cc] = __floats2half2_rn(v2, v3);
            }
        }
    }
}

// ---------------- fused flash attention: paired q-tiles + pad-row fusion ----------------
#define F2_QS   0
#define F2_KP   (64*72)
#define F2_VS   (F2_KP + 64*72)
#define F2_FL   (F2_VS + 64*72)
#define F2_BYTES (F2_FL*2 + 384*4)        // 29184

__global__ void __launch_bounds__(256) flash_attn_kernel(
    const __half* __restrict__ qv,
    const float* __restrict__ rmask, __half* __restrict__ ctxh, int mask_flag)
{
    extern __shared__ __align__(16) __half smh[];
    float* fl   = reinterpret_cast<float*>(smh + F2_FL);
    float* redm = fl;
    float* reds = fl + 128;
    float* m_s  = fl + 256;
    float* l_s  = fl + 320;

    const int z = blockIdx.y;           // b*H + h
    const int b = z >> 3, h = z & 7;
    const __half* Qg = qv + (long long)b * Ss * QVLD + h * 64;
    const __half* Vg = Qg + Dd;

    const int tid = threadIdx.x;
    const int warpId = tid >> 5, lane = tid & 31;
    const int grp = lane >> 2, tig = lane & 3;
    const int warpM = warpId >> 1, warpN = warpId & 1;
    const int row_a = warpM * 16 + grp;
    const int p = blockIdx.x;           // 0..3

    const uint32_t sbase = smem_u32(smh);
    const uint32_t aOff = (uint32_t)((warpM * 16 + (lane & 15)) * 72 + ((lane >> 4) << 3));
    const int bg = lane >> 3;
    const uint32_t bOff = (uint32_t)((warpN * 32 + ((bg >= 2) ? 8 : 0) + (lane & 7)) * 72
                                     + ((bg & 1) << 3));

    const float rm = (h < HSs) ? 1.f : rmask[z];
    float vsum = 0.f;
    const int padD = tid & 63, padJ0 = (tid >> 6) * 16;
    const __half2 qsc = __floats2half2_rn(0.125f, 0.125f);

    #pragma unroll 1
    for (int hv = 0; hv < 2; hv++) {
        const int qt = hv ? (7 - p) : p;
        const int q0 = qt * 64;
        const int nTiles = qt + 1;
        const bool doPad = (qt == 7);
        if (hv) __syncthreads();

        #pragma unroll
        for (int i = 0; i < 2; i++) {
            int id = tid + i * 256;
            int r = id >> 3, c8 = (id & 7) * 8;
            uint4 q = *(const uint4*)&Qg[(long long)(q0 + r) * QVLD + c8];
            __half2* qh = reinterpret_cast<__half2*>(&q);
            qh[0] = __hmul2(qh[0], qsc); qh[1] = __hmul2(qh[1], qsc);
            qh[2] = __hmul2(qh[2], qsc); qh[3] = __hmul2(qh[3], qsc);
            *(uint4*)&smh[F2_QS + r * 72 + c8] = q;
        }
        if (tid < 64) { m_s[tid] = -1e30f; l_s[tid] = 0.f; }

        float Oa[4][4];
        #pragma unroll
        for (int nt = 0; nt < 4; nt++)
            #pragma unroll
            for (int q = 0; q < 4; q++) Oa[nt][q] = 0.f;

        for (int kt = 0; kt < nTiles; kt++) {
            const int k0 = kt * 64;
            #pragma unroll
            for (int i = 0; i < 2; i++) {
                int id = tid + i * 256;
                int r = id >> 3, c8 = (id & 7) * 8;
                *(uint4*)&smh[F2_KP + r * 72 + c8] =
                    *(const uint4*)&Qg[(long long)(k0 + r) * QVLD + c8];
            }
            #pragma unroll
            for (int i = 0; i < 2; i++) {
                int id = tid + i * 256;
                int j = id >> 3, d0 = (id & 7) * 8;
                uint4 vv = *(const uint4*)&Vg[(long long)(k0 + j) * QVLD + d0];
                const __half* v8 = reinterpret_cast<const __half*>(&vv);
                #pragma unroll
                for (int t2 = 0; t2 < 8; t2++)
                    smh[F2_VS + (d0 + t2) * 72 + j] = v8[t2];
            }
            __syncthreads();

            if (doPad) {
                #pragma unroll
                for (int jj = 0; jj < 16; jj++)
                    vsum += __half2float(smh[F2_VS + padD * 72 + padJ0 + jj]);
            }

            float scf[4][4];
            #pragma unroll
            for (int nt = 0; nt < 4; nt++)
                #pragma unroll
                for (int q = 0; q < 4; q++) scf[nt][q] = 0.f;

            #pragma unroll
            for (int kk = 0; kk < 4; kk++) {
                const uint32_t kh = (uint32_t)(kk * 16) * 2u;
                uint32_t a0, a1, a2, a3;
                LDSM_X4(a0, a1, a2, a3, sbase + (F2_QS + aOff) * 2u + kh);
                uint32_t bf[4][2];
                LDSM_X4(bf[0][0], bf[0][1], bf[1][0], bf[1][1],
                        sbase + (F2_KP + bOff) * 2u + kh);
                LDSM_X4(bf[2][0], bf[2][1], bf[3][0], bf[3][1],
                        sbase + (F2_KP + bOff + 16 * 72) * 2u + kh);
                #pragma unroll
                for (int nt = 0; nt < 4; nt++)
                    mma_f16(scf[nt], a0, a1, a2, a3, bf[nt][0], bf[nt][1]);
            }

            if (kt == nTiles - 1) {
                int iA = q0 + row_a, iB = iA + 8;
                int limA = iA + (mask_flag ? 1 : 0);
                int limB = iB + (mask_flag ? 1 : 0);
                #pragma unroll
                for (int nt = 0; nt < 4; nt++) {
                    int j0 = k0 + warpN * 32 + nt * 8 + tig * 2;
                    if (j0     >= limA) scf[nt][0] = -1e30f;
                    if (j0 + 1 >= limA) scf[nt][1] = -1e30f;
                    if (j0     >= limB) scf[nt][2] = -1e30f;
                    if (j0 + 1 >= limB) scf[nt][3] = -1e30f;
                }
            }

            float mA_old = m_s[row_a], mB_old = m_s[row_a + 8];

            float tmA = -1e30f, tmB = -1e30f;
            #pragma unroll
            for (int nt = 0; nt < 4; nt++) {
                tmA = fmaxf(tmA, fmaxf(scf[nt][0], scf[nt][1]));
                tmB = fmaxf(tmB, fmaxf(scf[nt][2], scf[nt][3]));
            }
            tmA = fmaxf(tmA, __shfl_xor_sync(0xffffffffu, tmA, 1));
            tmA = fmaxf(tmA, __shfl_xor_sync(0xffffffffu, tmA, 2));
            tmB = fmaxf(tmB, __shfl_xor_sync(0xffffffffu, tmB, 1));
            tmB = fmaxf(tmB, __shfl_xor_sync(0xffffffffu, tmB, 2));
            if (tig == 0) {
                redm[warpN * 64 + row_a]     = tmA;
                redm[warpN * 64 + row_a + 8] = tmB;
            }
            __syncthreads();

            float mA = fmaxf(mA_old, fmaxf(redm[row_a],     redm[64 + row_a]));
            float mB = fmaxf(mB_old, fmaxf(redm[row_a + 8], redm[64 + row_a + 8]));
            float alA = __expf(mA_old - mA);
            float alB = __expf(mB_old - mB);

            float psA = 0.f, psB = 0.f;
            #pragma unroll
            for (int nt = 0; nt < 4; nt++) {
                float p0 = __expf(scf[nt][0] - mA);
                float p1 = __expf(scf[nt][1] - mA);
                float p2 = __expf(scf[nt][2] - mB);
                float p3 = __expf(scf[nt][3] - mB);
                psA += p0 + p1; psB += p2 + p3;
                int nc = warpN * 32 + nt * 8 + tig * 2;
                *(__half2*)&smh[F2_KP + (row_a)     * 72 + nc] = __floats2half2_rn(p0, p1);
                *(__half2*)&smh[F2_KP + (row_a + 8) * 72 + nc] = __floats2half2_rn(p2, p3);
                Oa[nt][0] *= alA; Oa[nt][1] *= alA;
                Oa[nt][2] *= alB; Oa[nt][3] *= alB;
            }
            psA += __shfl_xor_sync(0xffffffffu, psA, 1);
            psA += __shfl_xor_sync(0xffffffffu, psA, 2);
            psB += __shfl_xor_sync(0xffffffffu, psB, 1);
            psB += __shfl_xor_sync(0xffffffffu, psB, 2);
            if (tig == 0) {
                reds[warpN * 64 + row_a]     = psA;
                reds[warpN * 64 + row_a + 8] = psB;
            }
            if (warpN == 0 && tig == 0) {
                m_s[row_a]     = mA;
                m_s[row_a + 8] = mB;
            }
            __syncthreads();

            if (warpN == 0 && tig == 0) {
                l_s[row_a]     = alA * l_s[row_a]     + reds[row_a]     + reds[64 + row_a];
                l_s[row_a + 8] = alB * l_s[row_a + 8] + reds[row_a + 8] + reds[64 + row_a + 8];
            }

            #pragma unroll
            for (int kk = 0; kk < 4; kk++) {
                const uint32_t kh = (uint32_t)(kk * 16) * 2u;
                uint32_t a0, a1, a2, a3;
                LDSM_X4(a0, a1, a2, a3, sbase + (F2_KP + aOff) * 2u + kh);
                uint32_t bf[4][2];
                LDSM_X4(bf[0][0], bf[0][1], bf[1][0], bf[1][1],
                        sbase + (F2_VS + bOff) * 2u + kh);
                LDSM_X4(bf[2][0], bf[2][1], bf[3][0], bf[3][1],
                        sbase + (F2_VS + bOff + 16 * 72) * 2u + kh);
                #pragma unroll
                for (int nt = 0; nt < 4; nt++)
                    mma_f16(Oa[nt], a0, a1, a2, a3, bf[nt][0], bf[nt][1]);
            }
            __syncthreads();
        }

        float invA = rm / l_s[row_a];
        float invB = rm / l_s[row_a + 8];
        const bool skipA = (q0 + row_a == 0);
        #pragma unroll
        for (int nt = 0; nt < 4; nt++) {
            int col = h * 64 + warpN * 32 + nt * 8 + tig * 2;
            long long oA = ((long long)b * Ss + q0 + row_a) * Dd + col;
            long long oB = oA + 8LL * Dd;
            if (!skipA)
                *(__half2*)&ctxh[oA] = __floats2half2_rn(Oa[nt][0] * invA, Oa[nt][1] * invA);
            *(__half2*)&ctxh[oB] = __floats2half2_rn(Oa[nt][2] * invB, Oa[nt][3] * invB);
        }
    }

    if (p == 0) {
        __syncthreads();
        fl[tid] = vsum;
        __syncthreads();
        if (tid < 64) {
            float t2 = fl[tid] + fl[64 + tid] + fl[128 + tid] + fl[192 + tid];
            ctxh[(long long)b * Ss * Dd + h * 64 + tid] =
                __float2half_rn(t2 * (1.0f / Ss) * rm);
        }
    }
}

// ---------------- residual + LayerNorm (fp32 out + half mirror) ----------------
__global__ void add_ln_kernel(const float* __restrict__ resid, const float* __restrict__ delta,
                              const float* __restrict__ g, const float* __restrict__ b,
                              float* __restrict__ out, __half* __restrict__ outh)
{
    long long base = (long long)blockIdx.x * Dd;
    int tid = threadIdx.x;
    float v0 = resid[base + tid]       + delta[base + tid];
    float v1 = resid[base + tid + 256] + delta[base + tid + 256];
    float s  = v0 + v1;
    float sq = v0 * v0 + v1 * v1;

    __shared__ float rs[8], rq[8];
    #pragma unroll
    for (int o = 16; o; o >>= 1) {
        s  += __shfl_xor_sync(0xffffffffu, s,  o);
        sq += __shfl_xor_sync(0xffffffffu, sq, o);
    }
    if ((tid & 31) == 0) { rs[tid >> 5] = s; rq[tid >> 5] = sq; }
    __syncthreads();
    s = 0.f; sq = 0.f;
    #pragma unroll
    for (int w2 = 0; w2 < 8; w2++) { s += rs[w2]; sq += rq[w2]; }

    float mu   = s * (1.0f / Dd);
    float var  = sq * (1.0f / Dd) - mu * mu;
    float rstd = rsqrtf(var + 1e-5f);
    float o0 = g[tid]       * ((v0 - mu) * rstd) + b[tid];
    float o1 = g[tid + 256] * ((v1 - mu) * rstd) + b[tid + 256];
    out[base + tid]        = o0;
    out[base + tid + 256]  = o1;
    outh[base + tid]       = __float2half_rn(o0);
    outh[base + tid + 256] = __float2half_rn(o1);
}

// ---------------- head-routing gate: vectorized, atomic rmask ----------------
// wgt: per-layer transposed fp32 [NGATE][512]. One warp per token, one pass:
// lane owns 16 contiguous d (q: 2x uint4; wgt: 4x float4 per gate, L1-resident).
__global__ void gating_kernel(const __half* __restrict__ qv, const float* __restrict__ wgt,
                              float* __restrict__ rmask)
{
    int gw   = (int)((blockIdx.x * blockDim.x + threadIdx.x) >> 5);
    int lane = threadIdx.x & 31;
    if (gw >= Bn * Ss) return;
    const __half* q = qv + (long long)gw * QVLD + lane * 16;

    float qf[16];
    {
        uint4 q0 = *(const uint4*)q;
        uint4 q1 = *(const uint4*)(q + 8);
        const __half* h0 = reinterpret_cast<const __half*>(&q0);
        const __half* h1 = reinterpret_cast<const __half*>(&q1);
        #pragma unroll
        for (int t = 0; t < 8; t++) {
            qf[t]     = __half2float(h0[t]);
            qf[8 + t] = __half2float(h1[t]);
        }
    }

    float acc[NGATE];
    #pragma unroll
    for (int g2 = 0; g2 < NGATE; g2++) {
        const float4* wp = (const float4*)(wgt + g2 * Dd + lane * 16);
        float a = 0.f;
        #pragma unroll
        for (int c4 = 0; c4 < 4; c4++) {
            float4 wv = wp[c4];
            a += qf[c4 * 4 + 0] * wv.x + qf[c4 * 4 + 1] * wv.y
               + qf[c4 * 4 + 2] * wv.z + qf[c4 * 4 + 3] * wv.w;
        }
        acc[g2] = a;
    }
    #pragma unroll
    for (int g2 = 0; g2 < NGATE; g2++)
        #pragma unroll
        for (int o = 16; o; o >>= 1) acc[g2] += __shfl_xor_sync(0xffffffffu, acc[g2], o);

    if (lane == 0) {
        int i1 = 0;
        #pragma unroll
        for (int g2 = 1; g2 < NGATE; g2++) if (acc[g2] > acc[i1]) i1 = g2;
        int i2 = (i1 == 0) ? 1 : 0;
        #pragma unroll
        for (int g2 = 0; g2 < NGATE; g2++)
            if (g2 != i1 && acc[g2] > acc[i2]) i2 = g2;

        float mx = acc[i1], sum = 0.f, e[NGATE];
        #pragma unroll
        for (int g2 = 0; g2 < NGATE; g2++) { e[g2] = expf(acc[g2] - mx); sum += e[g2]; }
        float inv = (1.0f / sum) * (1.0f / Ss);
        int bb = gw >> 9;
        atomicAdd(&rmask[bb * Hh + HSs + i1], e[i1] * inv);
        atomicAdd(&rmask[bb * Hh + HSs + i2], e[i2] * inv);
    }
}

// ---------------- host orchestration ----------------
struct Wts {
    const float *wq, *bq, *wv, *bv, *wo, *bo, *wg;
    const float *ln1g, *ln1b, *fw1, *fb1, *fw2, *fb2, *ln2g, *ln2b;
};
struct HScr {
    float *tmp, *rmask, *bqv, *wgt;
    __half *xh, *yh, *qvh, *ctxh, *ffnh;
    __half *wqvh, *woh, *fw1h, *fw2h;
};

static void gemm_f32out(const __half* A, const __half* Bt, const float* bias, float* C,
                        int M, int Ncols, int ldc, int K, int relu)
{
    dim3 grid(Ncols / HBN, M / HBM);
    gemm_h_kernel<0><<<grid, 256, H_SMEM>>>(A, Bt, bias, C, nullptr, K, Ncols, ldc, relu);
}
static void gemm_h16out(const __half* A, const __half* Bt, const float* bias, __half* C,
                        int M, int Ncols, int ldc, int K, int relu)
{
    dim3 grid(Ncols / HBN, M / HBM);
    gemm_h_kernel<1><<<grid, 256, H_SMEM>>>(A, Bt, bias, nullptr, C, K, Ncols, ldc, relu);
}

static void run_block(const float* resid0, float* xq, __half* xqh, __half* xvh, int layer,
                      bool mask_flag, bool apply_pos,
                      const Wts& w, const HScr& s, float* finalOut)
{
    const int M = Bn * Ss;
    const long long DD = (long long)Dd * Dd;
    const __half* wqv = s.wqvh + (long long)layer * QVLD * Dd;

    cudaMemsetAsync(s.rmask, 0, Bn * Hh * sizeof(float));

    if (xqh == xvh) {
        gemm_h16out(xqh, wqv, s.bqv + layer * QVLD, s.qvh, M, QVLD, QVLD, Dd, 0);
    } else {
        gemm_h16out(xqh, wqv,                      w.bq + layer * Dd, s.qvh,      M, Dd, QVLD, Dd, 0);
        gemm_h16out(xvh, wqv + (long long)Dd * Dd, w.bv + layer * Dd, s.qvh + Dd, M, Dd, QVLD, Dd, 0);
    }

    gating_kernel<<<(Bn * Ss * 32 + 255) / 256, 256>>>(
        s.qvh, s.wgt + layer * NGATE * Dd, s.rmask);

    flash_attn_kernel<<<dim3(4, Bn * Hh), 256, F2_BYTES>>>(
        s.qvh, s.rmask, s.ctxh, mask_flag ? 1 : 0);

    gemm_f32out(s.ctxh, s.woh + layer * DD, w.bo + layer * Dd, s.tmp, M, Dd, Dd, Dd, 0);

    add_ln_kernel<<<M, 256>>>(resid0, s.tmp, w.ln1g + layer * Dd, w.ln1b + layer * Dd, xq, xqh);

    if (apply_pos) {
        gemm_h16out(xqh, s.fw1h + (long long)layer * Dd * DFFf, w.fb1 + layer * DFFf,
                    s.ffnh, M, DFFf, DFFf, Dd, 1);
        gemm_f32out(s.ffnh, s.fw2h + (long long)layer * Dd * DFFf, w.fb2 + layer * Dd,
                    s.tmp, M, Dd, Dd, DFFf, 0);
        float* out2 = finalOut ? finalOut : xq;
        add_ln_kernel<<<M, 256>>>(xq, s.tmp, w.ln2g + layer * Dd, w.ln2b + layer * Dd,
                                  out2, xqh);
    }
}

extern "C" void kernel_launch(void* const* d_in, const int* in_sizes, int n_in,
                              void* d_out, int out_size)
{
    const float* question    = (const float*)d_in[0];
    const float* interaction = (const float*)d_in[1];
    Wts w;
    w.wq   = (const float*)d_in[2];  w.bq   = (const float*)d_in[3];
    w.wv   = (const float*)d_in[4];  w.bv   = (const float*)d_in[5];
    w.wo   = (const float*)d_in[6];  w.bo   = (const float*)d_in[7];
    w.wg   = (const float*)d_in[8];
    w.ln1g = (const float*)d_in[9];  w.ln1b = (const float*)d_in[10];
    w.fw1  = (const float*)d_in[11]; w.fb1  = (const float*)d_in[12];
    w.fw2  = (const float*)d_in[13]; w.fb2  = (const float*)d_in[14];
    w.ln2g = (const float*)d_in[15]; w.ln2b = (const float*)d_in[16];

    cudaFuncSetAttribute(flash_attn_kernel,
                         cudaFuncAttributeMaxDynamicSharedMemorySize, F2_BYTES);
    cudaFuncSetAttribute(gemm_h_kernel<0>,
                         cudaFuncAttributeMaxDynamicSharedMemorySize, H_SMEM);
    cudaFuncSetAttribute(gemm_h_kernel<1>,
                         cudaFuncAttributeMaxDynamicSharedMemorySize, H_SMEM);

    float *gx, *gy;
    HScr s;
    cudaGetSymbolAddress((void**)&gx,      g_x);
    cudaGetSymbolAddress((void**)&gy,      g_y);
    cudaGetSymbolAddress((void**)&s.tmp,   g_tmp);
    cudaGetSymbolAddress((void**)&s.rmask, g_rmask);
    cudaGetSymbolAddress((void**)&s.bqv,   g_bqv);
    cudaGetSymbolAddress((void**)&s.wgt,   g_wgt);
    cudaGetSymbolAddress((void**)&s.xh,    g_xh);
    cudaGetSymbolAddress((void**)&s.yh,    g_yh);
    cudaGetSymbolAddress((void**)&s.qvh,   g_qvh);
    cudaGetSymbolAddress((void**)&s.ctxh,  g_ctxh);
    cudaGetSymbolAddress((void**)&s.ffnh,  g_ffnh);
    cudaGetSymbolAddress((void**)&s.wqvh,  g_wqvh);
    cudaGetSymbolAddress((void**)&s.woh,   g_woh);
    cudaGetSymbolAddress((void**)&s.fw1h,  g_fw1h);
    cudaGetSymbolAddress((void**)&s.fw2h,  g_fw2h);

    // prologue: 2 kernels
    {
        int n = Bn * Ss * Dd;
        f2h_bias_kernel<<<(n + 255) / 256, 256>>>(question, s.xh, interaction, s.yh, n,
                                                  w.bq, w.bv, s.bqv, w.wg, s.wgt);
        transp_all_kernel<<<8704, dim3(32, 8)>>>(w.wq, w.wv, w.wo, w.fw1, w.fw2,
                                                 s.wqvh, s.woh, s.fw1h, s.fw2h);
    }

    // knowledge encoder
    run_block(interaction, gy, s.yh, s.yh, 0, true,  false, w, s, nullptr);
    run_block(gy,          gy, s.yh, s.yh, 1, true,  false, w, s, nullptr);
    // question encoder
    run_block(question, gx, s.xh, s.xh, 2, true,  false, w, s, nullptr);
    run_block(gx,       gx, s.xh, s.yh, 3, false, true,  w, s, nullptr);
    run_block(gx,       gx, s.xh, s.xh, 4, true,  false, w, s, nullptr);
    run_block(gx,       gx, s.xh, s.yh, 5, false, true,  w, s, (float*)d_out);
}

// round 15
// speedup vs baseline: 1.0463x; 1.0463x over previous
#include <cuda_runtime.h>
#include <cuda_fp16.h>
#include <math.h>
#include <stdint.h>

#define Bn   16
#define Ss   512
#define Dd   512
#define Hh   8
#define HSs  2
#define DFFf 2048
#define NGATE 6   // H - HS
#define QVLD 1024 // combined q||v row stride

// ---------------- scratch (device globals; no allocation allowed) ----------------
__device__ float g_y[Bn*Ss*Dd];
__device__ float g_x[Bn*Ss*Dd];
__device__ float g_tmp[Bn*Ss*Dd];
__device__ float g_rmask[Bn*Hh];
__device__ float g_bqv[6*QVLD];
// half activations / weights
__device__ __half g_wgth[6*NGATE*Dd];     // per layer: [6 gates][512 d] half (transposed)
__device__ __half g_xh[Bn*Ss*Dd];
__device__ __half g_yh[Bn*Ss*Dd];
__device__ __half g_qvh[Bn*Ss*QVLD];      // q (cols 0-511) || v (512-1023)
__device__ __half g_ctxh[Bn*Ss*Dd];
__device__ __half g_ffnh[Bn*Ss*DFFf];
__device__ __half g_wqvh[6*QVLD*Dd];      // per layer: [1024 n][512 k], q rows then v rows
__device__ __half g_woh[6*Dd*Dd];
__device__ __half g_fw1h[6*Dd*DFFf];      // per layer: [DFF][D]
__device__ __half g_fw2h[6*DFFf*Dd];      // per layer: [D][DFF]

// ---------------- helpers ----------------
__device__ __forceinline__ void mma_f16(float c[4], uint32_t a0, uint32_t a1,
                                        uint32_t a2, uint32_t a3,
                                        uint32_t b0, uint32_t b1) {
    asm volatile(
        "mma.sync.aligned.m16n8k16.row.col.f32.f16.f16.f32 "
        "{%0,%1,%2,%3}, {%4,%5,%6,%7}, {%8,%9}, {%0,%1,%2,%3};"
        : "+f"(c[0]), "+f"(c[1]), "+f"(c[2]), "+f"(c[3])
        : "r"(a0), "r"(a1), "r"(a2), "r"(a3), "r"(b0), "r"(b1));
}

#define LDSM_X4(r0, r1, r2, r3, addr) \
    asm volatile("ldmatrix.sync.aligned.m8n8.x4.shared.b16 {%0,%1,%2,%3}, [%4];" \
                 : "=r"(r0), "=r"(r1), "=r"(r2), "=r"(r3) : "r"(addr))

__device__ __forceinline__ uint32_t smem_u32(const void* p) {
    uint32_t a;
    asm("{ .reg .u64 t; cvta.to.shared.u64 t, %1; cvt.u32.u64 %0, t; }"
        : "=r"(a) : "l"(p));
    return a;
}

__device__ __forceinline__ void cp_async16(uint32_t dst, const void* src) {
    asm volatile("cp.async.cg.shared.global [%0], [%1], 16;" :: "r"(dst), "l"(src));
}
__device__ __forceinline__ void cp_commit() {
    asm volatile("cp.async.commit_group;" ::: "memory");
}
template<int NN>
__device__ __forceinline__ void cp_wait() {
    asm volatile("cp.async.wait_group %0;" :: "n"(NN) : "memory");
}

// ---------------- unified weight convert+transpose (ONE launch) ----------------
__global__ void transp_all_kernel(const float* __restrict__ wq, const float* __restrict__ wv,
                                  const float* __restrict__ wo, const float* __restrict__ fw1,
                                  const float* __restrict__ fw2,
                                  __half* __restrict__ wqvh, __half* __restrict__ woh,
                                  __half* __restrict__ fw1h, __half* __restrict__ fw2h)
{
    __shared__ float t[32][33];
    const long long DD = (long long)Dd * Dd;
    const long long QV = (long long)QVLD * Dd;
    const long long DF = (long long)Dd * DFFf;

    int bid = blockIdx.x;
    const float* ip; __half* op; int R, C, cx, cy;
    if (bid < 4608) {
        int seg = bid / 1536, r2 = bid % 1536;
        int l = r2 >> 8, r = r2 & 255;
        cx = r & 15; cy = r >> 4; R = Dd; C = Dd;
        if (seg == 0)      { ip = wq + l * DD; op = wqvh + l * QV; }
        else if (seg == 1) { ip = wv + l * DD; op = wqvh + l * QV + DD; }
        else               { ip = wo + l * DD; op = woh + l * DD; }
    } else {
        int r2 = bid - 4608;
        int seg = r2 >> 10, r = r2 & 1023;
        int l = (seg < 2) ? 3 : 5;
        if ((seg & 1) == 0) { ip = fw1 + l * DF; op = fw1h + l * DF; R = Dd;  C = DFFf; cx = r & 63; cy = r >> 6; }
        else                { ip = fw2 + l * DF; op = fw2h + l * DF; R = DFFf; C = Dd;  cx = r & 15; cy = r >> 4; }
    }

    int c0 = cx * 32, r0 = cy * 32;
    int x = threadIdx.x, y0 = threadIdx.y;   // (32,8)
    #pragma unroll
    for (int i = 0; i < 32; i += 8)
        t[y0 + i][x] = ip[(long long)(r0 + y0 + i) * C + c0 + x];
    __syncthreads();
    #pragma unroll
    for (int i = 0; i < 32; i += 8)
        op[(long long)(c0 + y0 + i) * R + r0 + x] = __float2half_rn(t[x][y0 + i]);
}

// ---------------- embeddings fp32 -> half + qv bias concat + wg transpose(half) ----------------
__global__ void f2h_bias_kernel(const float* __restrict__ a, __half* __restrict__ ah,
                                const float* __restrict__ b, __half* __restrict__ bh, int n,
                                const float* __restrict__ bq, const float* __restrict__ bv,
                                float* __restrict__ bqv,
                                const float* __restrict__ wg, __half* __restrict__ wgth)
{
    int i = blockIdx.x * blockDim.x + threadIdx.x;
    if (i < n) {
        ah[i] = __float2half_rn(a[i]);
        bh[i] = __float2half_rn(b[i]);
    }
    if (i < 6 * QVLD) {
        int l = i >> 10, c = i & 1023;
        bqv[i] = (c < Dd) ? bq[l * Dd + c] : bv[l * Dd + c - Dd];
    }
    if (i < 6 * NGATE * Dd) {
        int l = i / (NGATE * Dd);
        int r = i % (NGATE * Dd);
        int g = r / Dd, d = r % Dd;
        wgth[i] = __float2half_rn(wg[(long long)l * Dd * NGATE + d * NGATE + g]);
    }
}

// ---------------- cp.async 3-stage FP16 GEMM (ldmatrix fragments) ----------------
#define HBM 128
#define HBN 128
#define HBK 64
#define HLDA 72
#define HSA (HBM * HLDA)           // 9216 halves
#define HSTAGE (2 * HSA)
#define H_SMEM (3 * HSTAGE * 2)    // 110592 bytes

template<int OM>
__global__ void __launch_bounds__(256) gemm_h_kernel(
    const __half* __restrict__ A, const __half* __restrict__ Bt,
    const float* __restrict__ bias, float* __restrict__ Cf, __half* __restrict__ Ch,
    int K, int Ncols, int ldc, int relu)
{
    extern __shared__ __align__(16) __half smh[];

    const int tid = threadIdx.x;
    const int warpId = tid >> 5;
    const int lane = tid & 31;
    const int grp = lane >> 2;
    const int tig = lane & 3;
    const int warpM = warpId & 1;
    const int warpN = warpId >> 1;
    const int row0 = blockIdx.y * HBM;
    const int col0 = blockIdx.x * HBN;

    const uint32_t sbase = smem_u32(smh);

    const uint32_t aOff = (uint32_t)((warpM * 64 + (lane & 15)) * HLDA + ((lane >> 4) << 3));
    const int bg = lane >> 3;
    const uint32_t bOff = (uint32_t)((warpN * 32 + ((bg >= 2) ? 8 : 0) + (lane & 7)) * HLDA
                                     + ((bg & 1) << 3));

    auto issue = [&](int kt) {
        const int st = kt % 3;
        const int k0 = kt * HBK;
        const uint32_t sA = sbase + (uint32_t)(st * HSTAGE) * 2u;
        const uint32_t sB = sA + (uint32_t)HSA * 2u;
        #pragma unroll
        for (int i = 0; i < 4; i++) {
            int f4 = tid + i * 256;
            int r = f4 >> 3, c8 = (f4 & 7) * 8;
            cp_async16(sA + (uint32_t)(r * HLDA + c8) * 2u,
                       &A[(long long)(row0 + r) * K + k0 + c8]);
        }
        #pragma unroll
        for (int i = 0; i < 4; i++) {
            int f4 = tid + i * 256;
            int n = f4 >> 3, c8 = (f4 & 7) * 8;
            cp_async16(sB + (uint32_t)(n * HLDA + c8) * 2u,
                       &Bt[(long long)(col0 + n) * K + k0 + c8]);
        }
        cp_commit();
    };

    float acc[4][4][4];
    #pragma unroll
    for (int mt = 0; mt < 4; mt++)
        #pragma unroll
        for (int nt = 0; nt < 4; nt++)
            #pragma unroll
            for (int q = 0; q < 4; q++) acc[mt][nt][q] = 0.f;

    const int KT = K / HBK;
    issue(0);
    if (KT > 1) issue(1);

    for (int kt = 0; kt < KT; kt++) {
        if (kt + 1 < KT) cp_wait<1>(); else cp_wait<0>();
        __syncthreads();
        if (kt + 2 < KT) issue(kt + 2);

        const uint32_t sA = sbase + (uint32_t)((kt % 3) * HSTAGE) * 2u;
        const uint32_t sB = sA + (uint32_t)HSA * 2u;

        #pragma unroll
        for (int kk = 0; kk < 4; kk++) {
            const uint32_t kh = (uint32_t)(kk * 16) * 2u;
            uint32_t af[4][4];
            #pragma unroll
            for (int mt = 0; mt < 4; mt++)
                LDSM_X4(af[mt][0], af[mt][1], af[mt][2], af[mt][3],
                        sA + (aOff + (uint32_t)(mt * 16 * HLDA)) * 2u + kh);
            uint32_t bf[4][2];
            LDSM_X4(bf[0][0], bf[0][1], bf[1][0], bf[1][1], sB + bOff * 2u + kh);
            LDSM_X4(bf[2][0], bf[2][1], bf[3][0], bf[3][1],
                    sB + (bOff + (uint32_t)(16 * HLDA)) * 2u + kh);
            #pragma unroll
            for (int mt = 0; mt < 4; mt++)
                #pragma unroll
                for (int nt = 0; nt < 4; nt++)
                    mma_f16(acc[mt][nt], af[mt][0], af[mt][1], af[mt][2], af[mt][3],
                            bf[nt][0], bf[nt][1]);
        }
    }

    #pragma unroll
    for (int mt = 0; mt < 4; mt++) {
        #pragma unroll
        for (int nt = 0; nt < 4; nt++) {
            int r0 = row0 + warpM * 64 + mt * 16 + grp;
            int cc = col0 + warpN * 32 + nt * 8 + tig * 2;
            float b0 = bias[cc], b1 = bias[cc + 1];
            float v0 = acc[mt][nt][0] + b0;
            float v1 = acc[mt][nt][1] + b1;
            float v2 = acc[mt][nt][2] + b0;
            float v3 = acc[mt][nt][3] + b1;
            if (relu) {
                v0 = fmaxf(v0, 0.f); v1 = fmaxf(v1, 0.f);
                v2 = fmaxf(v2, 0.f); v3 = fmaxf(v3, 0.f);
            }
            if (OM == 0) {
                *(float2*)&Cf[(long long)r0 * ldc + cc]       = make_float2(v0, v1);
                *(float2*)&Cf[(long long)(r0 + 8) * ldc + cc] = make_float2(v2, v3);
            } else {
                *(__half2*)&Ch[(long long)r0 * ldc + cc]       = __floats2half2_rn(v0, v1);
                *(__half2*)&Ch[(long long)(r0 + 8) * ldc + cc] = __floats2half2_rn(v2, v3);
            }
        }
    }
}

// ---------------- fused flash attention: paired q-tiles + pad-row fusion ----------------
#define F2_QS   0
#define F2_KP   (64*72)
#define F2_VS   (F2_KP + 64*72)
#define F2_FL   (F2_VS + 64*72)
#define F2_BYTES (F2_FL*2 + 384*4)        // 29184

__global__ void __launch_bounds__(256) flash_attn_kernel(
    const __half* __restrict__ qv,
    const float* __restrict__ rmask, __half* __restrict__ ctxh, int mask_flag)
{
    extern __shared__ __align__(16) __half smh[];
    float* fl   = reinterpret_cast<float*>(smh + F2_FL);
    float* redm = fl;
    float* reds = fl + 128;
    float* m_s  = fl + 256;
    float* l_s  = fl + 320;

    const int z = blockIdx.y;           // b*H + h
    const int b = z >> 3, h = z & 7;
    const __half* Qg = qv + (long long)b * Ss * QVLD + h * 64;
    const __half* Vg = Qg + Dd;

    const int tid = threadIdx.x;
    const int warpId = tid >> 5, lane = tid & 31;
    const int grp = lane >> 2, tig = lane & 3;
    const int warpM = warpId >> 1, warpN = warpId & 1;
    const int row_a = warpM * 16 + grp;
    const int p = blockIdx.x;           // 0..3

    const uint32_t sbase = smem_u32(smh);
    const uint32_t aOff = (uint32_t)((warpM * 16 + (lane & 15)) * 72 + ((lane >> 4) << 3));
    const int bg = lane >> 3;
    const uint32_t bOff = (uint32_t)((warpN * 32 + ((bg >= 2) ? 8 : 0) + (lane & 7)) * 72
                                     + ((bg & 1) << 3));

    const float rm = (h < HSs) ? 1.f : rmask[z];
    float vsum = 0.f;
    const int padD = tid & 63, padJ0 = (tid >> 6) * 16;
    const __half2 qsc = __floats2half2_rn(0.125f, 0.125f);

    #pragma unroll 1
    for (int hv = 0; hv < 2; hv++) {
        const int qt = hv ? (7 - p) : p;
        const int q0 = qt * 64;
        const int nTiles = qt + 1;
        const bool doPad = (qt == 7);
        if (hv) __syncthreads();

        #pragma unroll
        for (int i = 0; i < 2; i++) {
            int id = tid + i * 256;
            int r = id >> 3, c8 = (id & 7) * 8;
            uint4 q = *(const uint4*)&Qg[(long long)(q0 + r) * QVLD + c8];
            __half2* qh = reinterpret_cast<__half2*>(&q);
            qh[0] = __hmul2(qh[0], qsc); qh[1] = __hmul2(qh[1], qsc);
            qh[2] = __hmul2(qh[2], qsc); qh[3] = __hmul2(qh[3], qsc);
            *(uint4*)&smh[F2_QS + r * 72 + c8] = q;
        }
        if (tid < 64) { m_s[tid] = -1e30f; l_s[tid] = 0.f; }

        float Oa[4][4];
        #pragma unroll
        for (int nt = 0; nt < 4; nt++)
            #pragma unroll
            for (int q = 0; q < 4; q++) Oa[nt][q] = 0.f;

        for (int kt = 0; kt < nTiles; kt++) {
            const int k0 = kt * 64;
            #pragma unroll
            for (int i = 0; i < 2; i++) {
                int id = tid + i * 256;
                int r = id >> 3, c8 = (id & 7) * 8;
                *(uint4*)&smh[F2_KP + r * 72 + c8] =
                    *(const uint4*)&Qg[(long long)(k0 + r) * QVLD + c8];
            }
            #pragma unroll
            for (int i = 0; i < 2; i++) {
                int id = tid + i * 256;
                int j = id >> 3, d0 = (id & 7) * 8;
                uint4 vv = *(const uint4*)&Vg[(long long)(k0 + j) * QVLD + d0];
                const __half* v8 = reinterpret_cast<const __half*>(&vv);
                #pragma unroll
                for (int t2 = 0; t2 < 8; t2++)
                    smh[F2_VS + (d0 + t2) * 72 + j] = v8[t2];
            }
            __syncthreads();

            if (doPad) {
                #pragma unroll
                for (int jj = 0; jj < 16; jj++)
                    vsum += __half2float(smh[F2_VS + padD * 72 + padJ0 + jj]);
            }

            float scf[4][4];
            #pragma unroll
            for (int nt = 0; nt < 4; nt++)
                #pragma unroll
                for (int q = 0; q < 4; q++) scf[nt][q] = 0.f;

            #pragma unroll
            for (int kk = 0; kk < 4; kk++) {
                const uint32_t kh = (uint32_t)(kk * 16) * 2u;
                uint32_t a0, a1, a2, a3;
                LDSM_X4(a0, a1, a2, a3, sbase + (F2_QS + aOff) * 2u + kh);
                uint32_t bf[4][2];
                LDSM_X4(bf[0][0], bf[0][1], bf[1][0], bf[1][1],
                        sbase + (F2_KP + bOff) * 2u + kh);
                LDSM_X4(bf[2][0], bf[2][1], bf[3][0], bf[3][1],
                        sbase + (F2_KP + bOff + 16 * 72) * 2u + kh);
                #pragma unroll
                for (int nt = 0; nt < 4; nt++)
                    mma_f16(scf[nt], a0, a1, a2, a3, bf[nt][0], bf[nt][1]);
            }

            if (kt == nTiles - 1) {
                int iA = q0 + row_a, iB = iA + 8;
                int limA = iA + (mask_flag ? 1 : 0);
                int limB = iB + (mask_flag ? 1 : 0);
                #pragma unroll
                for (int nt = 0; nt < 4; nt++) {
                    int j0 = k0 + warpN * 32 + nt * 8 + tig * 2;
                    if (j0     >= limA) scf[nt][0] = -1e30f;
                    if (j0 + 1 >= limA) scf[nt][1] = -1e30f;
                    if (j0     >= limB) scf[nt][2] = -1e30f;
                    if (j0 + 1 >= limB) scf[nt][3] = -1e30f;
                }
            }

            float mA_old = m_s[row_a], mB_old = m_s[row_a + 8];

            float tmA = -1e30f, tmB = -1e30f;
            #pragma unroll
            for (int nt = 0; nt < 4; nt++) {
                tmA = fmaxf(tmA, fmaxf(scf[nt][0], scf[nt][1]));
                tmB = fmaxf(tmB, fmaxf(scf[nt][2], scf[nt][3]));
            }
            tmA = fmaxf(tmA, __shfl_xor_sync(0xffffffffu, tmA, 1));
            tmA = fmaxf(tmA, __shfl_xor_sync(0xffffffffu, tmA, 2));
            tmB = fmaxf(tmB, __shfl_xor_sync(0xffffffffu, tmB, 1));
            tmB = fmaxf(tmB, __shfl_xor_sync(0xffffffffu, tmB, 2));
            if (tig == 0) {
                redm[warpN * 64 + row_a]     = tmA;
                redm[warpN * 64 + row_a + 8] = tmB;
            }
            __syncthreads();

            float mA = fmaxf(mA_old, fmaxf(redm[row_a],     redm[64 + row_a]));
            float mB = fmaxf(mB_old, fmaxf(redm[row_a + 8], redm[64 + row_a + 8]));
            float alA = __expf(mA_old - mA);
            float alB = __expf(mB_old - mB);

            float psA = 0.f, psB = 0.f;
            #pragma unroll
            for (int nt = 0; nt < 4; nt++) {
                float p0 = __expf(scf[nt][0] - mA);
                float p1 = __expf(scf[nt][1] - mA);
                float p2 = __expf(scf[nt][2] - mB);
                float p3 = __expf(scf[nt][3] - mB);
                psA += p0 + p1; psB += p2 + p3;
                int nc = warpN * 32 + nt * 8 + tig * 2;
                *(__half2*)&smh[F2_KP + (row_a)     * 72 + nc] = __floats2half2_rn(p0, p1);
                *(__half2*)&smh[F2_KP + (row_a + 8) * 72 + nc] = __floats2half2_rn(p2, p3);
                Oa[nt][0] *= alA; Oa[nt][1] *= alA;
                Oa[nt][2] *= alB; Oa[nt][3] *= alB;
            }
            psA += __shfl_xor_sync(0xffffffffu, psA, 1);
            psA += __shfl_xor_sync(0xffffffffu, psA, 2);
            psB += __shfl_xor_sync(0xffffffffu, psB, 1);
            psB += __shfl_xor_sync(0xffffffffu, psB, 2);
            if (tig == 0) {
                reds[warpN * 64 + row_a]     = psA;
                reds[warpN * 64 + row_a + 8] = psB;
            }
            if (warpN == 0 && tig == 0) {
                m_s[row_a]     = mA;
                m_s[row_a + 8] = mB;
            }
            __syncthreads();

            if (warpN == 0 && tig == 0) {
                l_s[row_a]     = alA * l_s[row_a]     + reds[row_a]     + reds[64 + row_a];
                l_s[row_a + 8] = alB * l_s[row_a + 8] + reds[row_a + 8] + reds[64 + row_a + 8];
            }

            #pragma unroll
            for (int kk = 0; kk < 4; kk++) {
                const uint32_t kh = (uint32_t)(kk * 16) * 2u;
                uint32_t a0, a1, a2, a3;
                LDSM_X4(a0, a1, a2, a3, sbase + (F2_KP + aOff) * 2u + kh);
                uint32_t bf[4][2];
                LDSM_X4(bf[0][0], bf[0][1], bf[1][0], bf[1][1],
                        sbase + (F2_VS + bOff) * 2u + kh);
                LDSM_X4(bf[2][0], bf[2][1], bf[3][0], bf[3][1],
                        sbase + (F2_VS + bOff + 16 * 72) * 2u + kh);
                #pragma unroll
                for (int nt = 0; nt < 4; nt++)
                    mma_f16(Oa[nt], a0, a1, a2, a3, bf[nt][0], bf[nt][1]);
            }
            __syncthreads();
        }

        float invA = rm / l_s[row_a];
        float invB = rm / l_s[row_a + 8];
        const bool skipA = (q0 + row_a == 0);
        #pragma unroll
        for (int nt = 0; nt < 4; nt++) {
            int col = h * 64 + warpN * 32 + nt * 8 + tig * 2;
            long long oA = ((long long)b * Ss + q0 + row_a) * Dd + col;
            long long oB = oA + 8LL * Dd;
            if (!skipA)
                *(__half2*)&ctxh[oA] = __floats2half2_rn(Oa[nt][0] * invA, Oa[nt][1] * invA);
            *(__half2*)&ctxh[oB] = __floats2half2_rn(Oa[nt][2] * invB, Oa[nt][3] * invB);
        }
    }

    if (p == 0) {
        __syncthreads();
        fl[tid] = vsum;
        __syncthreads();
        if (tid < 64) {
            float t2 = fl[tid] + fl[64 + tid] + fl[128 + tid] + fl[192 + tid];
            ctxh[(long long)b * Ss * Dd + h * 64 + tid] =
                __float2half_rn(t2 * (1.0f / Ss) * rm);
        }
    }
}

// ---------------- residual + LayerNorm (fp32 out + half mirror) ----------------
__global__ void add_ln_kernel(const float* __restrict__ resid, const float* __restrict__ delta,
                              const float* __restrict__ g, const float* __restrict__ b,
                              float* __restrict__ out, __half* __restrict__ outh)
{
    long long base = (long long)blockIdx.x * Dd;
    int tid = threadIdx.x;
    float v0 = resid[base + tid]       + delta[base + tid];
    float v1 = resid[base + tid + 256] + delta[base + tid + 256];
    float s  = v0 + v1;
    float sq = v0 * v0 + v1 * v1;

    __shared__ float rs[8], rq[8];
    #pragma unroll
    for (int o = 16; o; o >>= 1) {
        s  += __shfl_xor_sync(0xffffffffu, s,  o);
        sq += __shfl_xor_sync(0xffffffffu, sq, o);
    }
    if ((tid & 31) == 0) { rs[tid >> 5] = s; rq[tid >> 5] = sq; }
    __syncthreads();
    s = 0.f; sq = 0.f;
    #pragma unroll
    for (int w2 = 0; w2 < 8; w2++) { s += rs[w2]; sq += rq[w2]; }

    float mu   = s * (1.0f / Dd);
    float var  = sq * (1.0f / Dd) - mu * mu;
    float rstd = rsqrtf(var + 1e-5f);
    float o0 = g[tid]       * ((v0 - mu) * rstd) + b[tid];
    float o1 = g[tid + 256] * ((v1 - mu) * rstd) + b[tid + 256];
    out[base + tid]        = o0;
    out[base + tid + 256]  = o1;
    outh[base + tid]       = __float2half_rn(o0);
    outh[base + tid + 256] = __float2half_rn(o1);
}

// ---------------- head-routing gate: fully-coalesced half loads, atomic rmask ----------------
// Lane owns d in {lane*8..+7} and {256+lane*8..+7}: q and wgth rows read as uint4
// with 16B inter-lane stride (4 L1 wavefronts per instruction).
__global__ void gating_kernel(const __half* __restrict__ qv, const __half* __restrict__ wgth,
                              float* __restrict__ rmask)
{
    int gw   = (int)((blockIdx.x * blockDim.x + threadIdx.x) >> 5);
    int lane = threadIdx.x & 31;
    if (gw >= Bn * Ss) return;
    const __half* q = qv + (long long)gw * QVLD;

    float qf[16];
    {
        uint4 q0 = *(const uint4*)(q + lane * 8);
        uint4 q1 = *(const uint4*)(q + 256 + lane * 8);
        const __half* h0 = reinterpret_cast<const __half*>(&q0);
        const __half* h1 = reinterpret_cast<const __half*>(&q1);
        #pragma unroll
        for (int t = 0; t < 8; t++) {
            qf[t]     = __half2float(h0[t]);
            qf[8 + t] = __half2float(h1[t]);
        }
    }

    float acc[NGATE];
    #pragma unroll
    for (int g2 = 0; g2 < NGATE; g2++) {
        uint4 w0 = *(const uint4*)(wgth + g2 * Dd + lane * 8);
        uint4 w1 = *(const uint4*)(wgth + g2 * Dd + 256 + lane * 8);
        const __half* p0 = reinterpret_cast<const __half*>(&w0);
        const __half* p1 = reinterpret_cast<const __half*>(&w1);
        float a = 0.f;
        #pragma unroll
        for (int t = 0; t < 8; t++) {
            a += qf[t]     * __half2float(p0[t]);
            a += qf[8 + t] * __half2float(p1[t]);
        }
        acc[g2] = a;
    }
    #pragma unroll
    for (int g2 = 0; g2 < NGATE; g2++)
        #pragma unroll
        for (int o = 16; o; o >>= 1) acc[g2] += __shfl_xor_sync(0xffffffffu, acc[g2], o);

    if (lane == 0) {
        int i1 = 0;
        #pragma unroll
        for (int g2 = 1; g2 < NGATE; g2++) if (acc[g2] > acc[i1]) i1 = g2;
        int i2 = (i1 == 0) ? 1 : 0;
        #pragma unroll
        for (int g2 = 0; g2 < NGATE; g2++)
            if (g2 != i1 && acc[g2] > acc[i2]) i2 = g2;

        float mx = acc[i1], sum = 0.f, e[NGATE];
        #pragma unroll
        for (int g2 = 0; g2 < NGATE; g2++) { e[g2] = expf(acc[g2] - mx); sum += e[g2]; }
        float inv = (1.0f / sum) * (1.0f / Ss);
        int bb = gw >> 9;
        atomicAdd(&rmask[bb * Hh + HSs + i1], e[i1] * inv);
        atomicAdd(&rmask[bb * Hh + HSs + i2], e[i2] * inv);
    }
}

// ---------------- host orchestration ----------------
struct Wts {
    const float *wq, *bq, *wv, *bv, *wo, *bo, *wg;
    const float *ln1g, *ln1b, *fw1, *fb1, *fw2, *fb2, *ln2g, *ln2b;
};
struct HScr {
    float *tmp, *rmask, *bqv;
    __half *wgth, *xh, *yh, *qvh, *ctxh, *ffnh;
    __half *wqvh, *woh, *fw1h, *fw2h;
};

static void gemm_f32out(const __half* A, const __half* Bt, const float* bias, float* C,
                        int M, int Ncols, int ldc, int K, int relu)
{
    dim3 grid(Ncols / HBN, M / HBM);
    gemm_h_kernel<0><<<grid, 256, H_SMEM>>>(A, Bt, bias, C, nullptr, K, Ncols, ldc, relu);
}
static void gemm_h16out(const __half* A, const __half* Bt, const float* bias, __half* C,
                        int M, int Ncols, int ldc, int K, int relu)
{
    dim3 grid(Ncols / HBN, M / HBM);
    gemm_h_kernel<1><<<grid, 256, H_SMEM>>>(A, Bt, bias, nullptr, C, K, Ncols, ldc, relu);
}

static void run_block(const float* resid0, float* xq, __half* xqh, __half* xvh, int layer,
                      bool mask_flag, bool apply_pos,
                      const Wts& w, const HScr& s, float* finalOut)
{
    const int M = Bn * Ss;
    const long long DD = (long long)Dd * Dd;
    const __half* wqv = s.wqvh + (long long)layer * QVLD * Dd;

    cudaMemsetAsync(s.rmask, 0, Bn * Hh * sizeof(float));

    if (xqh == xvh) {
        gemm_h16out(xqh, wqv, s.bqv + layer * QVLD, s.qvh, M, QVLD, QVLD, Dd, 0);
    } else {
        gemm_h16out(xqh, wqv,                      w.bq + layer * Dd, s.qvh,      M, Dd, QVLD, Dd, 0);
        gemm_h16out(xvh, wqv + (long long)Dd * Dd, w.bv + layer * Dd, s.qvh + Dd, M, Dd, QVLD, Dd, 0);
    }

    gating_kernel<<<(Bn * Ss * 32 + 255) / 256, 256>>>(
        s.qvh, s.wgth + layer * NGATE * Dd, s.rmask);

    flash_attn_kernel<<<dim3(4, Bn * Hh), 256, F2_BYTES>>>(
        s.qvh, s.rmask, s.ctxh, mask_flag ? 1 : 0);

    gemm_f32out(s.ctxh, s.woh + layer * DD, w.bo + layer * Dd, s.tmp, M, Dd, Dd, Dd, 0);

    add_ln_kernel<<<M, 256>>>(resid0, s.tmp, w.ln1g + layer * Dd, w.ln1b + layer * Dd, xq, xqh);

    if (apply_pos) {
        gemm_h16out(xqh, s.fw1h + (long long)layer * Dd * DFFf, w.fb1 + layer * DFFf,
                    s.ffnh, M, DFFf, DFFf, Dd, 1);
        gemm_f32out(s.ffnh, s.fw2h + (long long)layer * Dd * DFFf, w.fb2 + layer * Dd,
                    s.tmp, M, Dd, Dd, DFFf, 0);
        float* out2 = finalOut ? finalOut : xq;
        add_ln_kernel<<<M, 256>>>(xq, s.tmp, w.ln2g + layer * Dd, w.ln2b + layer * Dd,
                                  out2, xqh);
    }
}

extern "C" void kernel_launch(void* const* d_in, const int* in_sizes, int n_in,
                              void* d_out, int out_size)
{
    const float* question    = (const float*)d_in[0];
    const float* interaction = (const float*)d_in[1];
    Wts w;
    w.wq   = (const float*)d_in[2];  w.bq   = (const float*)d_in[3];
    w.wv   = (const float*)d_in[4];  w.bv   = (const float*)d_in[5];
    w.wo   = (const float*)d_in[6];  w.bo   = (const float*)d_in[7];
    w.wg   = (const float*)d_in[8];
    w.ln1g = (const float*)d_in[9];  w.ln1b = (const float*)d_in[10];
    w.fw1  = (const float*)d_in[11]; w.fb1  = (const float*)d_in[12];
    w.fw2  = (const float*)d_in[13]; w.fb2  = (const float*)d_in[14];
    w.ln2g = (const float*)d_in[15]; w.ln2b = (const float*)d_in[16];

    cudaFuncSetAttribute(flash_attn_kernel,
                         cudaFuncAttributeMaxDynamicSharedMemorySize, F2_BYTES);
    cudaFuncSetAttribute(gemm_h_kernel<0>,
                         cudaFuncAttributeMaxDynamicSharedMemorySize, H_SMEM);
    cudaFuncSetAttribute(gemm_h_kernel<1>,
                         cudaFuncAttributeMaxDynamicSharedMemorySize, H_SMEM);

    float *gx, *gy;
    HScr s;
    cudaGetSymbolAddress((void**)&gx,      g_x);
    cudaGetSymbolAddress((void**)&gy,      g_y);
    cudaGetSymbolAddress((void**)&s.tmp,   g_tmp);
    cudaGetSymbolAddress((void**)&s.rmask, g_rmask);
    cudaGetSymbolAddress((void**)&s.bqv,   g_bqv);
    cudaGetSymbolAddress((void**)&s.wgth,  g_wgth);
    cudaGetSymbolAddress((void**)&s.xh,    g_xh);
    cudaGetSymbolAddress((void**)&s.yh,    g_yh);
    cudaGetSymbolAddress((void**)&s.qvh,   g_qvh);
    cudaGetSymbolAddress((void**)&s.ctxh,  g_ctxh);
    cudaGetSymbolAddress((void**)&s.ffnh,  g_ffnh);
    cudaGetSymbolAddress((void**)&s.wqvh,  g_wqvh);
    cudaGetSymbolAddress((void**)&s.woh,   g_woh);
    cudaGetSymbolAddress((void**)&s.fw1h,  g_fw1h);
    cudaGetSymbolAddress((void**)&s.fw2h,  g_fw2h);

    // prologue: 2 kernels
    {
        int n = Bn * Ss * Dd;
        f2h_bias_kernel<<<(n + 255) / 256, 256>>>(question, s.xh, interaction, s.yh, n,
                                                  w.bq, w.bv, s.bqv, w.wg, s.wgth);
        transp_all_kernel<<<8704, dim3(32, 8)>>>(w.wq, w.wv, w.wo, w.fw1, w.fw2,
                                                 s.wqvh, s.woh, s.fw1h, s.fw2h);
    }

    // knowledge encoder
    run_block(interaction, gy, s.yh, s.yh, 0, true,  false, w, s, nullptr);
    run_block(gy,          gy, s.yh, s.yh, 1, true,  false, w, s, nullptr);
    // question encoder
    run_block(question, gx, s.xh, s.xh, 2, true,  false, w, s, nullptr);
    run_block(gx,       gx, s.xh, s.yh, 3, false, true,  w, s, nullptr);
    run_block(gx,       gx, s.xh, s.xh, 4, true,  false, w, s, nullptr);
    run_block(gx,       gx, s.xh, s.yh, 5, false, true,  w, s, (float*)d_out);
}

// round 16
// speedup vs baseline: 1.0535x; 1.0069x over previous
#include <cuda_runtime.h>
#include <cuda_fp16.h>
#include <math.h>
#include <stdint.h>

#define Bn   16
#define Ss   512
#define Dd   512
#define Hh   8
#define HSs  2
#define DFFf 2048
#define NGATE 6   // H - HS
#define QVLD 1024 // combined q||v row stride

// ---------------- scratch (device globals; no allocation allowed) ----------------
__device__ float g_y[Bn*Ss*Dd];
__device__ float g_x[Bn*Ss*Dd];
__device__ float g_tmp[Bn*Ss*Dd];
__device__ float g_rmask[Bn*Hh];
__device__ float g_bqv[6*QVLD];
// half activations / weights
__device__ __half g_wgth[6*NGATE*Dd];     // per layer: [6 gates][512 d] half (transposed)
__device__ __half g_xh[Bn*Ss*Dd];
__device__ __half g_yh[Bn*Ss*Dd];
__device__ __half g_qvh[Bn*Ss*QVLD];      // q (cols 0-511) || v (512-1023)
__device__ __half g_ctxh[Bn*Ss*Dd];
__device__ __half g_ffnh[Bn*Ss*DFFf];
__device__ __half g_wqvh[6*QVLD*Dd];      // per layer: [1024 n][512 k], q rows then v rows
__device__ __half g_woh[6*Dd*Dd];
__device__ __half g_fw1h[6*Dd*DFFf];      // per layer: [DFF][D]
__device__ __half g_fw2h[6*DFFf*Dd];      // per layer: [D][DFF]

// ---------------- helpers ----------------
__device__ __forceinline__ void mma_f16(float c[4], uint32_t a0, uint32_t a1,
                                        uint32_t a2, uint32_t a3,
                                        uint32_t b0, uint32_t b1) {
    asm volatile(
        "mma.sync.aligned.m16n8k16.row.col.f32.f16.f16.f32 "
        "{%0,%1,%2,%3}, {%4,%5,%6,%7}, {%8,%9}, {%0,%1,%2,%3};"
        : "+f"(c[0]), "+f"(c[1]), "+f"(c[2]), "+f"(c[3])
        : "r"(a0), "r"(a1), "r"(a2), "r"(a3), "r"(b0), "r"(b1));
}

#define LDSM_X4(r0, r1, r2, r3, addr) \
    asm volatile("ldmatrix.sync.aligned.m8n8.x4.shared.b16 {%0,%1,%2,%3}, [%4];" \
                 : "=r"(r0), "=r"(r1), "=r"(r2), "=r"(r3) : "r"(addr))

__device__ __forceinline__ uint32_t smem_u32(const void* p) {
    uint32_t a;
    asm("{ .reg .u64 t; cvta.to.shared.u64 t, %1; cvt.u32.u64 %0, t; }"
        : "=r"(a) : "l"(p));
    return a;
}

__device__ __forceinline__ void cp_async16(uint32_t dst, const void* src) {
    asm volatile("cp.async.cg.shared.global [%0], [%1], 16;" :: "r"(dst), "l"(src));
}
__device__ __forceinline__ void cp_commit() {
    asm volatile("cp.async.commit_group;" ::: "memory");
}
template<int NN>
__device__ __forceinline__ void cp_wait() {
    asm volatile("cp.async.wait_group %0;" :: "n"(NN) : "memory");
}

// ---------------- unified weight convert+transpose (ONE launch) ----------------
__global__ void transp_all_kernel(const float* __restrict__ wq, const float* __restrict__ wv,
                                  const float* __restrict__ wo, const float* __restrict__ fw1,
                                  const float* __restrict__ fw2,
                                  __half* __restrict__ wqvh, __half* __restrict__ woh,
                                  __half* __restrict__ fw1h, __half* __restrict__ fw2h)
{
    __shared__ float t[32][33];
    const long long DD = (long long)Dd * Dd;
    const long long QV = (long long)QVLD * Dd;
    const long long DF = (long long)Dd * DFFf;

    int bid = blockIdx.x;
    const float* ip; __half* op; int R, C, cx, cy;
    if (bid < 4608) {
        int seg = bid / 1536, r2 = bid % 1536;
        int l = r2 >> 8, r = r2 & 255;
        cx = r & 15; cy = r >> 4; R = Dd; C = Dd;
        if (seg == 0)      { ip = wq + l * DD; op = wqvh + l * QV; }
        else if (seg == 1) { ip = wv + l * DD; op = wqvh + l * QV + DD; }
        else               { ip = wo + l * DD; op = woh + l * DD; }
    } else {
        int r2 = bid - 4608;
        int seg = r2 >> 10, r = r2 & 1023;
        int l = (seg < 2) ? 3 : 5;
        if ((seg & 1) == 0) { ip = fw1 + l * DF; op = fw1h + l * DF; R = Dd;  C = DFFf; cx = r & 63; cy = r >> 6; }
        else                { ip = fw2 + l * DF; op = fw2h + l * DF; R = DFFf; C = Dd;  cx = r & 15; cy = r >> 4; }
    }

    int c0 = cx * 32, r0 = cy * 32;
    int x = threadIdx.x, y0 = threadIdx.y;   // (32,8)
    #pragma unroll
    for (int i = 0; i < 32; i += 8)
        t[y0 + i][x] = ip[(long long)(r0 + y0 + i) * C + c0 + x];
    __syncthreads();
    #pragma unroll
    for (int i = 0; i < 32; i += 8)
        op[(long long)(c0 + y0 + i) * R + r0 + x] = __float2half_rn(t[x][y0 + i]);
}

// ---------------- embeddings fp32 -> half + qv bias concat + wg transpose(half) ----------------
__global__ void f2h_bias_kernel(const float* __restrict__ a, __half* __restrict__ ah,
                                const float* __restrict__ b, __half* __restrict__ bh, int n,
                                const float* __restrict__ bq, const float* __restrict__ bv,
                                float* __restrict__ bqv,
                                const float* __restrict__ wg, __half* __restrict__ wgth)
{
    int i = blockIdx.x * blockDim.x + threadIdx.x;
    if (i < n) {
        ah[i] = __float2half_rn(a[i]);
        bh[i] = __float2half_rn(b[i]);
    }
    if (i < 6 * QVLD) {
        int l = i >> 10, c = i & 1023;
        bqv[i] = (c < Dd) ? bq[l * Dd + c] : bv[l * Dd + c - Dd];
    }
    if (i < 6 * NGATE * Dd) {
        int l = i / (NGATE * Dd);
        int r = i % (NGATE * Dd);
        int g = r / Dd, d = r % Dd;
        wgth[i] = __float2half_rn(wg[(long long)l * Dd * NGATE + d * NGATE + g]);
    }
}

// ---------------- cp.async 3-stage FP16 GEMM (ldmatrix fragments) ----------------
#define HBM 128
#define HBN 128
#define HBK 64
#define HLDA 72
#define HSA (HBM * HLDA)           // 9216 halves
#define HSTAGE (2 * HSA)
#define H_SMEM (3 * HSTAGE * 2)    // 110592 bytes

template<int OM>
__global__ void __launch_bounds__(256) gemm_h_kernel(
    const __half* __restrict__ A, const __half* __restrict__ Bt,
    const float* __restrict__ bias, float* __restrict__ Cf, __half* __restrict__ Ch,
    int K, int Ncols, int ldc, int relu)
{
    extern __shared__ __align__(16) __half smh[];

    const int tid = threadIdx.x;
    const int warpId = tid >> 5;
    const int lane = tid & 31;
    const int grp = lane >> 2;
    const int tig = lane & 3;
    const int warpM = warpId & 1;
    const int warpN = warpId >> 1;
    const int row0 = blockIdx.y * HBM;
    const int col0 = blockIdx.x * HBN;

    const uint32_t sbase = smem_u32(smh);

    const uint32_t aOff = (uint32_t)((warpM * 64 + (lane & 15)) * HLDA + ((lane >> 4) << 3));
    const int bg = lane >> 3;
    const uint32_t bOff = (uint32_t)((warpN * 32 + ((bg >= 2) ? 8 : 0) + (lane & 7)) * HLDA
                                     + ((bg & 1) << 3));

    auto issue = [&](int kt) {
        const int st = kt % 3;
        const int k0 = kt * HBK;
        const uint32_t sA = sbase + (uint32_t)(st * HSTAGE) * 2u;
        const uint32_t sB = sA + (uint32_t)HSA * 2u;
        #pragma unroll
        for (int i = 0; i < 4; i++) {
            int f4 = tid + i * 256;
            int r = f4 >> 3, c8 = (f4 & 7) * 8;
            cp_async16(sA + (uint32_t)(r * HLDA + c8) * 2u,
                       &A[(long long)(row0 + r) * K + k0 + c8]);
        }
        #pragma unroll
        for (int i = 0; i < 4; i++) {
            int f4 = tid + i * 256;
            int n = f4 >> 3, c8 = (f4 & 7) * 8;
            cp_async16(sB + (uint32_t)(n * HLDA + c8) * 2u,
                       &Bt[(long long)(col0 + n) * K + k0 + c8]);
        }
        cp_commit();
    };

    float acc[4][4][4];
    #pragma unroll
    for (int mt = 0; mt < 4; mt++)
        #pragma unroll
        for (int nt = 0; nt < 4; nt++)
            #pragma unroll
            for (int q = 0; q < 4; q++) acc[mt][nt][q] = 0.f;

    const int KT = K / HBK;
    issue(0);
    if (KT > 1) issue(1);

    for (int kt = 0; kt < KT; kt++) {
        if (kt + 1 < KT) cp_wait<1>(); else cp_wait<0>();
        __syncthreads();
        if (kt + 2 < KT) issue(kt + 2);

        const uint32_t sA = sbase + (uint32_t)((kt % 3) * HSTAGE) * 2u;
        const uint32_t sB = sA + (uint32_t)HSA * 2u;

        #pragma unroll
        for (int kk = 0; kk < 4; kk++) {
            const uint32_t kh = (uint32_t)(kk * 16) * 2u;
            uint32_t af[4][4];
            #pragma unroll
            for (int mt = 0; mt < 4; mt++)
                LDSM_X4(af[mt][0], af[mt][1], af[mt][2], af[mt][3],
                        sA + (aOff + (uint32_t)(mt * 16 * HLDA)) * 2u + kh);
            uint32_t bf[4][2];
            LDSM_X4(bf[0][0], bf[0][1], bf[1][0], bf[1][1], sB + bOff * 2u + kh);
            LDSM_X4(bf[2][0], bf[2][1], bf[3][0], bf[3][1],
                    sB + (bOff + (uint32_t)(16 * HLDA)) * 2u + kh);
            #pragma unroll
            for (int mt = 0; mt < 4; mt++)
                #pragma unroll
                for (int nt = 0; nt < 4; nt++)
                    mma_f16(acc[mt][nt], af[mt][0], af[mt][1], af[mt][2], af[mt][3],
                            bf[nt][0], bf[nt][1]);
        }
    }

    #pragma unroll
    for (int mt = 0; mt < 4; mt++) {
        #pragma unroll
        for (int nt = 0; nt < 4; nt++) {
            int r0 = row0 + warpM * 64 + mt * 16 + grp;
            int cc = col0 + warpN * 32 + nt * 8 + tig * 2;
            float b0 = bias[cc], b1 = bias[cc + 1];
            float v0 = acc[mt][nt][0] + b0;
            float v1 = acc[mt][nt][1] + b1;
            float v2 = acc[mt][nt][2] + b0;
            float v3 = acc[mt][nt][3] + b1;
            if (relu) {
                v0 = fmaxf(v0, 0.f); v1 = fmaxf(v1, 0.f);
                v2 = fmaxf(v2, 0.f); v3 = fmaxf(v3, 0.f);
            }
            if (OM == 0) {
                *(float2*)&Cf[(long long)r0 * ldc + cc]       = make_float2(v0, v1);
                *(float2*)&Cf[(long long)(r0 + 8) * ldc + cc] = make_float2(v2, v3);
            } else {
                *(__half2*)&Ch[(long long)r0 * ldc + cc]       = __floats2half2_rn(v0, v1);
                *(__half2*)&Ch[(long long)(r0 + 8) * ldc + cc] = __floats2half2_rn(v2, v3);
            }
        }
    }
}

// ---------------- fused flash attention: paired q-tiles + pad-row fusion ----------------
#define F2_QS   0
#define F2_KP   (64*72)
#define F2_VS   (F2_KP + 64*72)
#define F2_FL   (F2_VS + 64*72)
#define F2_BYTES (F2_FL*2 + 384*4)        // 29184

__global__ void __launch_bounds__(256) flash_attn_kernel(
    const __half* __restrict__ qv,
    const float* __restrict__ rmask, __half* __restrict__ ctxh, int mask_flag)
{
    extern __shared__ __align__(16) __half smh[];
    float* fl   = reinterpret_cast<float*>(smh + F2_FL);
    float* redm = fl;
    float* reds = fl + 128;
    float* m_s  = fl + 256;
    float* l_s  = fl + 320;

    const int z = blockIdx.y;           // b*H + h
    const int b = z >> 3, h = z & 7;
    const __half* Qg = qv + (long long)b * Ss * QVLD + h * 64;
    const __half* Vg = Qg + Dd;

    const int tid = threadIdx.x;
    const int warpId = tid >> 5, lane = tid & 31;
    const int grp = lane >> 2, tig = lane & 3;
    const int warpM = warpId >> 1, warpN = warpId & 1;
    const int row_a = warpM * 16 + grp;
    const int p = blockIdx.x;           // 0..3

    const uint32_t sbase = smem_u32(smh);
    const uint32_t aOff = (uint32_t)((warpM * 16 + (lane & 15)) * 72 + ((lane >> 4) << 3));
    const int bg = lane >> 3;
    const uint32_t bOff = (uint32_t)((warpN * 32 + ((bg >= 2) ? 8 : 0) + (lane & 7)) * 72
                                     + ((bg & 1) << 3));

    const float rm = (h < HSs) ? 1.f : rmask[z];
    float vsum = 0.f;
    const int padD = tid & 63, padJ0 = (tid >> 6) * 16;
    const __half2 qsc = __floats2half2_rn(0.125f, 0.125f);

    #pragma unroll 1
    for (int hv = 0; hv < 2; hv++) {
        const int qt = hv ? (7 - p) : p;
        const int q0 = qt * 64;
        const int nTiles = qt + 1;
        const bool doPad = (qt == 7);
        if (hv) __syncthreads();

        #pragma unroll
        for (int i = 0; i < 2; i++) {
            int id = tid + i * 256;
            int r = id >> 3, c8 = (id & 7) * 8;
            uint4 q = *(const uint4*)&Qg[(long long)(q0 + r) * QVLD + c8];
            __half2* qh = reinterpret_cast<__half2*>(&q);
            qh[0] = __hmul2(qh[0], qsc); qh[1] = __hmul2(qh[1], qsc);
            qh[2] = __hmul2(qh[2], qsc); qh[3] = __hmul2(qh[3], qsc);
            *(uint4*)&smh[F2_QS + r * 72 + c8] = q;
        }
        if (tid < 64) { m_s[tid] = -1e30f; l_s[tid] = 0.f; }

        float Oa[4][4];
        #pragma unroll
        for (int nt = 0; nt < 4; nt++)
            #pragma unroll
            for (int q = 0; q < 4; q++) Oa[nt][q] = 0.f;

        for (int kt = 0; kt < nTiles; kt++) {
            const int k0 = kt * 64;
            #pragma unroll
            for (int i = 0; i < 2; i++) {
                int id = tid + i * 256;
                int r = id >> 3, c8 = (id & 7) * 8;
                *(uint4*)&smh[F2_KP + r * 72 + c8] =
                    *(const uint4*)&Qg[(long long)(k0 + r) * QVLD + c8];
            }
            #pragma unroll
            for (int i = 0; i < 2; i++) {
                int id = tid + i * 256;
                int j = id >> 3, d0 = (id & 7) * 8;
                uint4 vv = *(const uint4*)&Vg[(long long)(k0 + j) * QVLD + d0];
                const __half* v8 = reinterpret_cast<const __half*>(&vv);
                #pragma unroll
                for (int t2 = 0; t2 < 8; t2++)
                    smh[F2_VS + (d0 + t2) * 72 + j] = v8[t2];
            }
            __syncthreads();

            if (doPad) {
                #pragma unroll
                for (int jj = 0; jj < 16; jj++)
                    vsum += __half2float(smh[F2_VS + padD * 72 + padJ0 + jj]);
            }

            float scf[4][4];
            #pragma unroll
            for (int nt = 0; nt < 4; nt++)
                #pragma unroll
                for (int q = 0; q < 4; q++) scf[nt][q] = 0.f;

            #pragma unroll
            for (int kk = 0; kk < 4; kk++) {
                const uint32_t kh = (uint32_t)(kk * 16) * 2u;
                uint32_t a0, a1, a2, a3;
                LDSM_X4(a0, a1, a2, a3, sbase + (F2_QS + aOff) * 2u + kh);
                uint32_t bf[4][2];
                LDSM_X4(bf[0][0], bf[0][1], bf[1][0], bf[1][1],
                        sbase + (F2_KP + bOff) * 2u + kh);
                LDSM_X4(bf[2][0], bf[2][1], bf[3][0], bf[3][1],
                        sbase + (F2_KP + bOff + 16 * 72) * 2u + kh);
                #pragma unroll
                for (int nt = 0; nt < 4; nt++)
                    mma_f16(scf[nt], a0, a1, a2, a3, bf[nt][0], bf[nt][1]);
            }

            if (kt == nTiles - 1) {
                int iA = q0 + row_a, iB = iA + 8;
                int limA = iA + (mask_flag ? 1 : 0);
                int limB = iB + (mask_flag ? 1 : 0);
                #pragma unroll
                for (int nt = 0; nt < 4; nt++) {
                    int j0 = k0 + warpN * 32 + nt * 8 + tig * 2;
                    if (j0     >= limA) scf[nt][0] = -1e30f;
                    if (j0 + 1 >= limA) scf[nt][1] = -1e30f;
                    if (j0     >= limB) scf[nt][2] = -1e30f;
                    if (j0 + 1 >= limB) scf[nt][3] = -1e30f;
                }
            }

            float mA_old = m_s[row_a], mB_old = m_s[row_a + 8];

            float tmA = -1e30f, tmB = -1e30f;
            #pragma unroll
            for (int nt = 0; nt < 4; nt++) {
                tmA = fmaxf(tmA, fmaxf(scf[nt][0], scf[nt][1]));
                tmB = fmaxf(tmB, fmaxf(scf[nt][2], scf[nt][3]));
            }
            tmA = fmaxf(tmA, __shfl_xor_sync(0xffffffffu, tmA, 1));
            tmA = fmaxf(tmA, __shfl_xor_sync(0xffffffffu, tmA, 2));
            tmB = fmaxf(tmB, __shfl_xor_sync(0xffffffffu, tmB, 1));
            tmB = fmaxf(tmB, __shfl_xor_sync(0xffffffffu, tmB, 2));
            if (tig == 0) {
                redm[warpN * 64 + row_a]     = tmA;
                redm[warpN * 64 + row_a + 8] = tmB;
            }
            __syncthreads();

            float mA = fmaxf(mA_old, fmaxf(redm[row_a],     redm[64 + row_a]));
            float mB = fmaxf(mB_old, fmaxf(redm[row_a + 8], redm[64 + row_a + 8]));
            float alA = __expf(mA_old - mA);
            float alB = __expf(mB_old - mB);

            float psA = 0.f, psB = 0.f;
            #pragma unroll
            for (int nt = 0; nt < 4; nt++) {
                float p0 = __expf(scf[nt][0] - mA);
                float p1 = __expf(scf[nt][1] - mA);
                float p2 = __expf(scf[nt][2] - mB);
                float p3 = __expf(scf[nt][3] - mB);
                psA += p0 + p1; psB += p2 + p3;
                int nc = warpN * 32 + nt * 8 + tig * 2;
                *(__half2*)&smh[F2_KP + (row_a)     * 72 + nc] = __floats2half2_rn(p0, p1);
                *(__half2*)&smh[F2_KP + (row_a + 8) * 72 + nc] = __floats2half2_rn(p2, p3);
                Oa[nt][0] *= alA; Oa[nt][1] *= alA;
                Oa[nt][2] *= alB; Oa[nt][3] *= alB;
            }
            psA += __shfl_xor_sync(0xffffffffu, psA, 1);
            psA += __shfl_xor_sync(0xffffffffu, psA, 2);
            psB += __shfl_xor_sync(0xffffffffu, psB, 1);
            psB += __shfl_xor_sync(0xffffffffu, psB, 2);
            if (tig == 0) {
                reds[warpN * 64 + row_a]     = psA;
                reds[warpN * 64 + row_a + 8] = psB;
            }
            if (warpN == 0 && tig == 0) {
                m_s[row_a]     = mA;
                m_s[row_a + 8] = mB;
            }
            __syncthreads();

            if (warpN == 0 && tig == 0) {
                l_s[row_a]     = alA * l_s[row_a]     + reds[row_a]     + reds[64 + row_a];
                l_s[row_a + 8] = alB * l_s[row_a + 8] + reds[row_a + 8] + reds[64 + row_a + 8];
            }

            #pragma unroll
            for (int kk = 0; kk < 4; kk++) {
                const uint32_t kh = (uint32_t)(kk * 16) * 2u;
                uint32_t a0, a1, a2, a3;
                LDSM_X4(a0, a1, a2, a3, sbase + (F2_KP + aOff) * 2u + kh);
                uint32_t bf[4][2];
                LDSM_X4(bf[0][0], bf[0][1], bf[1][0], bf[1][1],
                        sbase + (F2_VS + bOff) * 2u + kh);
                LDSM_X4(bf[2][0], bf[2][1], bf[3][0], bf[3][1],
                        sbase + (F2_VS + bOff + 16 * 72) * 2u + kh);
                #pragma unroll
                for (int nt = 0; nt < 4; nt++)
                    mma_f16(Oa[nt], a0, a1, a2, a3, bf[nt][0], bf[nt][1]);
            }
            __syncthreads();
        }

        float invA = rm / l_s[row_a];
        float invB = rm / l_s[row_a + 8];
        const bool skipA = (q0 + row_a == 0);
        #pragma unroll
        for (int nt = 0; nt < 4; nt++) {
            int col = h * 64 + warpN * 32 + nt * 8 + tig * 2;
            long long oA = ((long long)b * Ss + q0 + row_a) * Dd + col;
            long long oB = oA + 8LL * Dd;
            if (!skipA)
                *(__half2*)&ctxh[oA] = __floats2half2_rn(Oa[nt][0] * invA, Oa[nt][1] * invA);
            *(__half2*)&ctxh[oB] = __floats2half2_rn(Oa[nt][2] * invB, Oa[nt][3] * invB);
        }
    }

    if (p == 0) {
        __syncthreads();
        fl[tid] = vsum;
        __syncthreads();
        if (tid < 64) {
            float t2 = fl[tid] + fl[64 + tid] + fl[128 + tid] + fl[192 + tid];
            ctxh[(long long)b * Ss * Dd + h * 64 + tid] =
                __float2half_rn(t2 * (1.0f / Ss) * rm);
        }
    }
}

// ---------------- residual + LayerNorm (fp32 out + half mirror) ----------------
__global__ void add_ln_kernel(const float* __restrict__ resid, const float* __restrict__ delta,
                              const float* __restrict__ g, const float* __restrict__ b,
                              float* __restrict__ out, __half* __restrict__ outh)
{
    long long base = (long long)blockIdx.x * Dd;
    int tid = threadIdx.x;
    float v0 = resid[base + tid]       + delta[base + tid];
    float v1 = resid[base + tid + 256] + delta[base + tid + 256];
    float s  = v0 + v1;
    float sq = v0 * v0 + v1 * v1;

    __shared__ float rs[8], rq[8];
    #pragma unroll
    for (int o = 16; o; o >>= 1) {
        s  += __shfl_xor_sync(0xffffffffu, s,  o);
        sq += __shfl_xor_sync(0xffffffffu, sq, o);
    }
    if ((tid & 31) == 0) { rs[tid >> 5] = s; rq[tid >> 5] = sq; }
    __syncthreads();
    s = 0.f; sq = 0.f;
    #pragma unroll
    for (int w2 = 0; w2 < 8; w2++) { s += rs[w2]; sq += rq[w2]; }

    float mu   = s * (1.0f / Dd);
    float var  = sq * (1.0f / Dd) - mu * mu;
    float rstd = rsqrtf(var + 1e-5f);
    float o0 = g[tid]       * ((v0 - mu) * rstd) + b[tid];
    float o1 = g[tid + 256] * ((v1 - mu) * rstd) + b[tid + 256];
    out[base + tid]        = o0;
    out[base + tid + 256]  = o1;
    outh[base + tid]       = __float2half_rn(o0);
    outh[base + tid + 256] = __float2half_rn(o1);
}

// ---------------- head-routing gate: HFMA2 accumulation, coalesced, atomic rmask ----------------
__global__ void gating_kernel(const __half* __restrict__ qv, const __half* __restrict__ wgth,
                              float* __restrict__ rmask)
{
    int gw   = (int)((blockIdx.x * blockDim.x + threadIdx.x) >> 5);
    int lane = threadIdx.x & 31;
    if (gw >= Bn * Ss) return;
    const __half* q = qv + (long long)gw * QVLD;

    // 16 halves per lane as 8 half2 (coalesced uint4 loads)
    uint4 q0 = *(const uint4*)(q + lane * 8);
    uint4 q1 = *(const uint4*)(q + 256 + lane * 8);
    const __half2* qh0 = reinterpret_cast<const __half2*>(&q0);
    const __half2* qh1 = reinterpret_cast<const __half2*>(&q1);

    float acc[NGATE];
    #pragma unroll
    for (int g2 = 0; g2 < NGATE; g2++) {
        uint4 w0 = *(const uint4*)(wgth + g2 * Dd + lane * 8);
        uint4 w1 = *(const uint4*)(wgth + g2 * Dd + 256 + lane * 8);
        const __half2* wh0 = reinterpret_cast<const __half2*>(&w0);
        const __half2* wh1 = reinterpret_cast<const __half2*>(&w1);
        __half2 a = __floats2half2_rn(0.f, 0.f);
        #pragma unroll
        for (int t = 0; t < 4; t++) {
            a = __hfma2(qh0[t], wh0[t], a);
            a = __hfma2(qh1[t], wh1[t], a);
        }
        acc[g2] = __low2float(a) + __high2float(a);
    }
    #pragma unroll
    for (int g2 = 0; g2 < NGATE; g2++)
        #pragma unroll
        for (int o = 16; o; o >>= 1) acc[g2] += __shfl_xor_sync(0xffffffffu, acc[g2], o);

    if (lane == 0) {
        int i1 = 0;
        #pragma unroll
        for (int g2 = 1; g2 < NGATE; g2++) if (acc[g2] > acc[i1]) i1 = g2;
        int i2 = (i1 == 0) ? 1 : 0;
        #pragma unroll
        for (int g2 = 0; g2 < NGATE; g2++)
            if (g2 != i1 && acc[g2] > acc[i2]) i2 = g2;

        float mx = acc[i1], sum = 0.f, e[NGATE];
        #pragma unroll
        for (int g2 = 0; g2 < NGATE; g2++) { e[g2] = expf(acc[g2] - mx); sum += e[g2]; }
        float inv = (1.0f / sum) * (1.0f / Ss);
        int bb = gw >> 9;
        atomicAdd(&rmask[bb * Hh + HSs + i1], e[i1] * inv);
        atomicAdd(&rmask[bb * Hh + HSs + i2], e[i2] * inv);
    }
}

// ---------------- host orchestration ----------------
struct Wts {
    const float *wq, *bq, *wv, *bv, *wo, *bo, *wg;
    const float *ln1g, *ln1b, *fw1, *fb1, *fw2, *fb2, *ln2g, *ln2b;
};
struct HScr {
    float *tmp, *rmask, *bqv;
    __half *wgth, *xh, *yh, *qvh, *ctxh, *ffnh;
    __half *wqvh, *woh, *fw1h, *fw2h;
};

static void gemm_f32out(const __half* A, const __half* Bt, const float* bias, float* C,
                        int M, int Ncols, int ldc, int K, int relu)
{
    dim3 grid(Ncols / HBN, M / HBM);
    gemm_h_kernel<0><<<grid, 256, H_SMEM>>>(A, Bt, bias, C, nullptr, K, Ncols, ldc, relu);
}
static void gemm_h16out(const __half* A, const __half* Bt, const float* bias, __half* C,
                        int M, int Ncols, int ldc, int K, int relu)
{
    dim3 grid(Ncols / HBN, M / HBM);
    gemm_h_kernel<1><<<grid, 256, H_SMEM>>>(A, Bt, bias, nullptr, C, K, Ncols, ldc, relu);
}

static void run_block(const float* resid0, float* xq, __half* xqh, __half* xvh, int layer,
                      bool mask_flag, bool apply_pos,
                      const Wts& w, const HScr& s, float* finalOut)
{
    const int M = Bn * Ss;
    const long long DD = (long long)Dd * Dd;
    const __half* wqv = s.wqvh + (long long)layer * QVLD * Dd;

    cudaMemsetAsync(s.rmask, 0, Bn * Hh * sizeof(float));

    if (xqh == xvh) {
        gemm_h16out(xqh, wqv, s.bqv + layer * QVLD, s.qvh, M, QVLD, QVLD, Dd, 0);
    } else {
        gemm_h16out(xqh, wqv,                      w.bq + layer * Dd, s.qvh,      M, Dd, QVLD, Dd, 0);
        gemm_h16out(xvh, wqv + (long long)Dd * Dd, w.bv + layer * Dd, s.qvh + Dd, M, Dd, QVLD, Dd, 0);
    }

    gating_kernel<<<(Bn * Ss * 32 + 255) / 256, 256>>>(
        s.qvh, s.wgth + layer * NGATE * Dd, s.rmask);

    flash_attn_kernel<<<dim3(4, Bn * Hh), 256, F2_BYTES>>>(
        s.qvh, s.rmask, s.ctxh, mask_flag ? 1 : 0);

    gemm_f32out(s.ctxh, s.woh + layer * DD, w.bo + layer * Dd, s.tmp, M, Dd, Dd, Dd, 0);

    add_ln_kernel<<<M, 256>>>(resid0, s.tmp, w.ln1g + layer * Dd, w.ln1b + layer * Dd, xq, xqh);

    if (apply_pos) {
        gemm_h16out(xqh, s.fw1h + (long long)layer * Dd * DFFf, w.fb1 + layer * DFFf,
                    s.ffnh, M, DFFf, DFFf, Dd, 1);
        gemm_f32out(s.ffnh, s.fw2h + (long long)layer * Dd * DFFf, w.fb2 + layer * Dd,
                    s.tmp, M, Dd, Dd, DFFf, 0);
        float* out2 = finalOut ? finalOut : xq;
        add_ln_kernel<<<M, 256>>>(xq, s.tmp, w.ln2g + layer * Dd, w.ln2b + layer * Dd,
                                  out2, xqh);
    }
}

extern "C" void kernel_launch(void* const* d_in, const int* in_sizes, int n_in,
                              void* d_out, int out_size)
{
    const float* question    = (const float*)d_in[0];
    const float* interaction = (const float*)d_in[1];
    Wts w;
    w.wq   = (const float*)d_in[2];  w.bq   = (const float*)d_in[3];
    w.wv   = (const float*)d_in[4];  w.bv   = (const float*)d_in[5];
    w.wo   = (const float*)d_in[6];  w.bo   = (const float*)d_in[7];
    w.wg   = (const float*)d_in[8];
    w.ln1g = (const float*)d_in[9];  w.ln1b = (const float*)d_in[10];
    w.fw1  = (const float*)d_in[11]; w.fb1  = (const float*)d_in[12];
    w.fw2  = (const float*)d_in[13]; w.fb2  = (const float*)d_in[14];
    w.ln2g = (const float*)d_in[15]; w.ln2b = (const float*)d_in[16];

    cudaFuncSetAttribute(flash_attn_kernel,
                         cudaFuncAttributeMaxDynamicSharedMemorySize, F2_BYTES);
    cudaFuncSetAttribute(gemm_h_kernel<0>,
                         cudaFuncAttributeMaxDynamicSharedMemorySize, H_SMEM);
    cudaFuncSetAttribute(gemm_h_kernel<1>,
                         cudaFuncAttributeMaxDynamicSharedMemorySize, H_SMEM);

    float *gx, *gy;
    HScr s;
    cudaGetSymbolAddress((void**)&gx,      g_x);
    cudaGetSymbolAddress((void**)&gy,      g_y);
    cudaGetSymbolAddress((void**)&s.tmp,   g_tmp);
    cudaGetSymbolAddress((void**)&s.rmask, g_rmask);
    cudaGetSymbolAddress((void**)&s.bqv,   g_bqv);
    cudaGetSymbolAddress((void**)&s.wgth,  g_wgth);
    cudaGetSymbolAddress((void**)&s.xh,    g_xh);
    cudaGetSymbolAddress((void**)&s.yh,    g_yh);
    cudaGetSymbolAddress((void**)&s.qvh,   g_qvh);
    cudaGetSymbolAddress((void**)&s.ctxh,  g_ctxh);
    cudaGetSymbolAddress((void**)&s.ffnh,  g_ffnh);
    cudaGetSymbolAddress((void**)&s.wqvh,  g_wqvh);
    cudaGetSymbolAddress((void**)&s.woh,   g_woh);
    cudaGetSymbolAddress((void**)&s.fw1h,  g_fw1h);
    cudaGetSymbolAddress((void**)&s.fw2h,  g_fw2h);

    // prologue: 2 kernels
    {
        int n = Bn * Ss * Dd;
        f2h_bias_kernel<<<(n + 255) / 256, 256>>>(question, s.xh, interaction, s.yh, n,
                                                  w.bq, w.bv, s.bqv, w.wg, s.wgth);
        transp_all_kernel<<<8704, dim3(32, 8)>>>(w.wq, w.wv, w.wo, w.fw1, w.fw2,
                                                 s.wqvh, s.woh, s.fw1h, s.fw2h);
    }

    // knowledge encoder
    run_block(interaction, gy, s.yh, s.yh, 0, true,  false, w, s, nullptr);
    run_block(gy,          gy, s.yh, s.yh, 1, true,  false, w, s, nullptr);
    // question encoder
    run_block(question, gx, s.xh, s.xh, 2, true,  false, w, s, nullptr);
    run_block(gx,       gx, s.xh, s.yh, 3, false, true,  w, s, nullptr);
    run_block(gx,       gx, s.xh, s.xh, 4, true,  false, w, s, nullptr);
    run_block(gx,       gx, s.xh, s.yh, 5, false, true,  w, s, (float*)d_out);
}